// round 5
// baseline (speedup 1.0000x reference)
#include <cuda_runtime.h>
#include <cuda_bf16.h>
#include <math.h>
#include <stdint.h>

#define HIDDEN 2048
#define INTER  768
#define NE     32
#define TOPK   8
#define MAXT   512
#define MAXP   (MAXT * TOPK)

typedef unsigned short ushort_t;

// ---- scratch (device globals) ----
__device__ float g_topw[MAXP];
__device__ int   g_topi[MAXP];
__device__ int   g_cnt[NE];
__device__ int   g_off[NE];
__device__ int   g_pt[MAXP];
__device__ int   g_t2p[MAXP];
__device__ ushort_t g_x_hi[(size_t)MAXT * HIDDEN];
__device__ ushort_t g_x_lo[(size_t)MAXT * HIDDEN];
__device__ ushort_t g_act_hi[(size_t)MAXP * INTER];
__device__ ushort_t g_act_lo[(size_t)MAXP * INTER];
__device__ float g_eout[(size_t)MAXP * HIDDEN];

// ================= helpers =================
__device__ __forceinline__ uint32_t smem_u32(const void* p) {
    uint32_t a;
    asm("{ .reg .u64 t; cvta.to.shared.u64 t, %1; cvt.u32.u64 %0, t; }" : "=r"(a) : "l"(p));
    return a;
}
__device__ __forceinline__ void cpa16(uint32_t dst, const void* src) {
    asm volatile("cp.async.ca.shared.global [%0], [%1], 16;" :: "r"(dst), "l"(src));
}
__device__ __forceinline__ void cpa8z(uint32_t dst, const void* src, int zf) {
    asm volatile("cp.async.ca.shared.global [%0], [%1], 8, %2;" :: "r"(dst), "l"(src), "r"(zf));
}
#define CP_COMMIT() asm volatile("cp.async.commit_group;" ::: "memory")
#define CP_WAIT0()  asm volatile("cp.async.wait_group 0;" ::: "memory")

__device__ __forceinline__ void ldsm4(uint32_t* r, uint32_t addr) {
    asm volatile("ldmatrix.sync.aligned.m8n8.x4.shared.b16 {%0,%1,%2,%3}, [%4];"
        : "=r"(r[0]), "=r"(r[1]), "=r"(r[2]), "=r"(r[3]) : "r"(addr));
}

__device__ __forceinline__ unsigned short bfh(float v) { return __bfloat16_as_ushort(__float2bfloat16(v)); }
__device__ __forceinline__ float bff(unsigned short u) { return __bfloat162float(__ushort_as_bfloat16(u)); }
__device__ __forceinline__ void split2(float a, float b, uint32_t& hi, uint32_t& lo) {
    unsigned short ha = bfh(a), hb = bfh(b);
    float ra = a - bff(ha), rb = b - bff(hb);
    hi = (uint32_t)ha | ((uint32_t)hb << 16);
    lo = (uint32_t)bfh(ra) | ((uint32_t)bfh(rb) << 16);
}
__device__ __forceinline__ void mma16816(float* c, const uint32_t* a, const uint32_t* b) {
    asm volatile(
        "mma.sync.aligned.m16n8k16.row.col.f32.bf16.bf16.f32 "
        "{%0,%1,%2,%3}, {%4,%5,%6,%7}, {%8,%9}, {%0,%1,%2,%3};"
        : "+f"(c[0]), "+f"(c[1]), "+f"(c[2]), "+f"(c[3])
        : "r"(a[0]), "r"(a[1]), "r"(a[2]), "r"(a[3]), "r"(b[0]), "r"(b[1]));
}

#define AS 40     // A smem row stride (ushorts); 80B rows, LDSM conflict-free
#define BW 272    // B interleaved kp-row stride (ushorts) = 544B
#define RS 68     // raw fp32 row stride (floats)

// ================= small kernels =================
__global__ void prep_x_kernel(const float* __restrict__ x, int nTot) {
    int i = (blockIdx.x * 256 + threadIdx.x) * 4;
    if (i < nTot) {
        float4 v = *(const float4*)(x + i);
        uint2 H, L;
        split2(v.x, v.y, H.x, L.x);
        split2(v.z, v.w, H.y, L.y);
        *(uint2*)&g_x_hi[i] = H;
        *(uint2*)&g_x_lo[i] = L;
    }
}

__global__ void router_kernel(const float* __restrict__ x, const float* __restrict__ gw) {
    int t = blockIdx.x;
    __shared__ float xs[HIDDEN];
    __shared__ float logits[NE];
    int tid = threadIdx.x;
    for (int i = tid; i < HIDDEN; i += 128) xs[i] = x[(size_t)t * HIDDEN + i];
    __syncthreads();
    int warp = tid >> 5, lane = tid & 31;
    for (int e8 = 0; e8 < 8; e8++) {
        int e = warp * 8 + e8;
        const float* w = gw + (size_t)e * HIDDEN;
        float s = 0.f;
        for (int h = lane; h < HIDDEN; h += 32) s += xs[h] * w[h];
        #pragma unroll
        for (int o = 16; o; o >>= 1) s += __shfl_xor_sync(0xffffffffu, s, o);
        if (lane == 0) logits[e] = s;
    }
    __syncthreads();
    if (tid == 0) {
        float mx = -1e30f;
        for (int e = 0; e < NE; e++) mx = fmaxf(mx, logits[e]);
        float p[NE];
        for (int e = 0; e < NE; e++) p[e] = expf(logits[e] - mx);
        bool used[NE] = {};
        float wsum = 0.f; int idx[TOPK]; float wv[TOPK];
        for (int k = 0; k < TOPK; k++) {
            float best = -1.f; int bi = 0;
            for (int e = 0; e < NE; e++)
                if (!used[e] && p[e] > best) { best = p[e]; bi = e; }
            used[bi] = true; idx[k] = bi; wv[k] = best; wsum += best;
        }
        float inv = 1.f / wsum;
        for (int k = 0; k < TOPK; k++) {
            g_topi[t * TOPK + k] = idx[k];
            g_topw[t * TOPK + k] = wv[k] * inv;
        }
    }
}

__global__ void build_kernel(int T) {
    __shared__ int cnts[NE];
    int e = threadIdx.x;
    int np = T * TOPK;
    int c = 0;
    for (int p = 0; p < np; p++) if (g_topi[p] == e) c++;
    cnts[e] = c;
    __syncthreads();
    int off = 0;
    for (int i = 0; i < e; i++) off += cnts[i];
    g_off[e] = off;
    g_cnt[e] = c;
    int j = off;
    for (int p = 0; p < np; p++)
        if (g_topi[p] == e) { g_pt[j] = p >> 3; g_t2p[p] = j; j++; }
}

__global__ void combine_kernel(float* __restrict__ y) {
    int t = blockIdx.x, tid = threadIdx.x;
    __shared__ int   pj[TOPK];
    __shared__ float pw[TOPK];
    if (tid < TOPK) { pj[tid] = g_t2p[t * TOPK + tid]; pw[tid] = g_topw[t * TOPK + tid]; }
    __syncthreads();
    #pragma unroll
    for (int h = 0; h < 2; h++) {
        int c = h * 1024 + tid * 4;
        float4 acc = make_float4(0.f, 0.f, 0.f, 0.f);
        #pragma unroll
        for (int k = 0; k < TOPK; k++) {
            const float4 v = *(const float4*)(g_eout + (size_t)pj[k] * HIDDEN + c);
            float w = pw[k];
            acc.x += w * v.x; acc.y += w * v.y; acc.z += w * v.z; acc.w += w * v.w;
        }
        *(float4*)(y + (size_t)t * HIDDEN + c) = acc;
    }
}

// ================= E1 =================
// smem: toks[64] @0 | A bufs @256 (2 x (hi5120+lo5120)) | raw W @20736 (2 x (G8704+U8704))
//       | interleaved bfW @55552 (G 8704 + U 8704)
#define E1_A    256
#define E1_RAW  20736
#define E1_BFW  55552
#define E1_SMEM 72960

extern __shared__ __align__(16) char dsm[];

__device__ __forceinline__ void e1_prefetch(int tid, const int* toks, uint32_t sb,
                                            const float* gp, const float* up_,
                                            int k0, int b) {
    uint32_t Abase = sb + E1_A + b * 10240;
    #pragma unroll
    for (int q = 0; q < 2; q++) {
        int lin = q * 256 + tid;
        int m = lin >> 3, c = lin & 7;
        int t = toks[m];
        int zf = (t >= 0) ? 8 : 0;
        size_t so = (size_t)(t >= 0 ? t : 0) * HIDDEN + k0 + c * 4;
        uint32_t d = Abase + m * 80 + c * 8;
        cpa8z(d, g_x_hi + so, zf);
        cpa8z(d + 5120, g_x_lo + so, zf);
    }
    uint32_t Rbase = sb + E1_RAW + b * 17408;
    #pragma unroll
    for (int q = 0; q < 2; q++) {
        int lin = q * 256 + tid;
        int k = lin >> 4, n4 = lin & 15;
        uint32_t d = Rbase + k * 272 + n4 * 16;
        size_t so = (size_t)(k0 + k) * INTER + n4 * 4;
        cpa16(d, gp + so);
        cpa16(d + 8704, up_ + so);
    }
    CP_COMMIT();
}

__global__ __launch_bounds__(256, 2)
void e1_kernel(const float* __restrict__ gate_proj,
               const float* __restrict__ up_proj) {
    int e = blockIdx.x;
    int n = g_cnt[e];
    int mbase = blockIdx.y * 64;
    if (mbase >= n) return;
    int off = g_off[e];
    int nbase = blockIdx.z * 64;

    uint32_t sb = smem_u32(dsm);
    int tid = threadIdx.x, wid = tid >> 5, lane = tid & 31;
    int* toks = (int*)dsm;
    if (tid < 64) { int m = mbase + tid; toks[tid] = (m < n) ? g_pt[off + m] : -1; }
    __syncthreads();

    const float* gp  = gate_proj + (size_t)e * HIDDEN * INTER + nbase;
    const float* up_ = up_proj   + (size_t)e * HIDDEN * INTER + nbase;

    int wm = wid >> 2, wn = wid & 3;
    int g = lane >> 2, tg = lane & 3;
    // ldmatrix per-lane row offset within a 16x16 A-frag (bytes)
    int lq = lane >> 3, lr = lane & 7;
    int lmoff = ((lq & 1) * 8 + lr) * (AS * 2) + (lq >> 1) * 16;

    float accg[2][2][4] = {};
    float accu[2][2][4] = {};

    ushort_t* Gus = (ushort_t*)(dsm + E1_BFW);
    ushort_t* Uus = Gus + 4352;

    e1_prefetch(tid, toks, sb, gp, up_, 0, 0);

    for (int it = 0; it < HIDDEN / 32; it++) {
        int b = it & 1;
        CP_WAIT0();
        __syncthreads();
        if (it + 1 < HIDDEN / 32)
            e1_prefetch(tid, toks, sb, gp, up_, (it + 1) * 32, b ^ 1);

        // ---- convert raw W -> interleaved split bf16 [kp][n][hi2,lo2] ----
        {
            const float* rawG = (const float*)(dsm + E1_RAW + b * 17408);
            const float* rawU = rawG + 2176;
            int nn = tid & 63, kg = tid >> 6;
            #pragma unroll
            for (int kpi = 0; kpi < 4; kpi++) {
                int kp = kpi * 4 + kg;
                int k = kp * 2;
                int wi = kp * BW + nn * 4;
                uint32_t hi, lo;
                split2(rawG[k * RS + nn], rawG[(k + 1) * RS + nn], hi, lo);
                *(uint2*)&Gus[wi] = make_uint2(hi, lo);
                split2(rawU[k * RS + nn], rawU[(k + 1) * RS + nn], hi, lo);
                *(uint2*)&Uus[wi] = make_uint2(hi, lo);
            }
        }
        __syncthreads();

        uint32_t Ah_base = sb + E1_A + b * 10240 + (wm * 32) * 80 + lmoff;
        #pragma unroll
        for (int kk = 0; kk < 32; kk += 16) {
            uint32_t ah[2][4], al[2][4];
            #pragma unroll
            for (int mf = 0; mf < 2; mf++) {
                uint32_t aaddr = Ah_base + mf * (16 * 80) + kk * 2;
                ldsm4(ah[mf], aaddr);
                ldsm4(al[mf], aaddr + 5120);
            }
            int kp0 = (kk >> 1) + tg;
            {
                uint32_t bh[2][2], bl[2][2];
                #pragma unroll
                for (int nf = 0; nf < 2; nf++) {
                    int ni = (wn * 16 + nf * 8 + g) * 4;
                    uint2 v0 = *(const uint2*)&Gus[kp0 * BW + ni];
                    uint2 v1 = *(const uint2*)&Gus[(kp0 + 4) * BW + ni];
                    bh[nf][0] = v0.x; bh[nf][1] = v1.x;
                    bl[nf][0] = v0.y; bl[nf][1] = v1.y;
                }
                #pragma unroll
                for (int mf = 0; mf < 2; mf++)
                #pragma unroll
                for (int nf = 0; nf < 2; nf++) {
                    mma16816(accg[mf][nf], ah[mf], bh[nf]);
                    mma16816(accg[mf][nf], ah[mf], bl[nf]);
                    mma16816(accg[mf][nf], al[mf], bh[nf]);
                }
            }
            {
                uint32_t bh[2][2], bl[2][2];
                #pragma unroll
                for (int nf = 0; nf < 2; nf++) {
                    int ni = (wn * 16 + nf * 8 + g) * 4;
                    uint2 v0 = *(const uint2*)&Uus[kp0 * BW + ni];
                    uint2 v1 = *(const uint2*)&Uus[(kp0 + 4) * BW + ni];
                    bh[nf][0] = v0.x; bh[nf][1] = v1.x;
                    bl[nf][0] = v0.y; bl[nf][1] = v1.y;
                }
                #pragma unroll
                for (int mf = 0; mf < 2; mf++)
                #pragma unroll
                for (int nf = 0; nf < 2; nf++) {
                    mma16816(accu[mf][nf], ah[mf], bh[nf]);
                    mma16816(accu[mf][nf], ah[mf], bl[nf]);
                    mma16816(accu[mf][nf], al[mf], bh[nf]);
                }
            }
        }
    }

    // ---- epilogue: silu(g)*u -> split bf16 -> g_act ----
    #pragma unroll
    for (int mf = 0; mf < 2; mf++)
    #pragma unroll
    for (int nf = 0; nf < 2; nf++)
    #pragma unroll
    for (int i = 0; i < 4; i++) {
        int m = mbase + wm * 32 + mf * 16 + g + (i >> 1) * 8;
        if (m >= n) continue;
        int col = nbase + wn * 16 + nf * 8 + 2 * tg + (i & 1);
        float gv = accg[mf][nf][i], uv = accu[mf][nf][i];
        float a = (gv / (1.f + __expf(-gv))) * uv;
        unsigned short h = bfh(a);
        float r = a - bff(h);
        size_t ai = (size_t)(off + m) * INTER + col;
        g_act_hi[ai] = h;
        g_act_lo[ai] = bfh(r);
    }
}

// ================= E2 =================
// smem: A bufs @0 (2 x (hi5120+lo5120)) | raw B @20480 (2 x 8704) | interleaved bfB @37888 (8704)
#define E2_A    0
#define E2_RAW  20480
#define E2_BF   37888
#define E2_SMEM 46592

__device__ __forceinline__ void e2_prefetch(int tid, int off, int mbase, int n, uint32_t sb,
                                            const float* dp, int k0, int b) {
    uint32_t Abase = sb + E2_A + b * 10240;
    #pragma unroll
    for (int q = 0; q < 2; q++) {
        int lin = q * 256 + tid;
        int m = lin >> 3, c = lin & 7;
        bool valid = (mbase + m) < n;
        int zf = valid ? 8 : 0;
        size_t so = valid ? ((size_t)(off + mbase + m) * INTER + k0 + c * 4) : 0;
        uint32_t d = Abase + m * 80 + c * 8;
        cpa8z(d, g_act_hi + so, zf);
        cpa8z(d + 5120, g_act_lo + so, zf);
    }
    uint32_t Rbase = sb + E2_RAW + b * 8704;
    #pragma unroll
    for (int q = 0; q < 2; q++) {
        int lin = q * 256 + tid;
        int k = lin >> 4, n4 = lin & 15;
        cpa16(Rbase + k * 272 + n4 * 16, dp + (size_t)(k0 + k) * HIDDEN + n4 * 4);
    }
    CP_COMMIT();
}

__global__ __launch_bounds__(256, 2)
void e2_kernel(const float* __restrict__ down_proj) {
    int e = blockIdx.x;
    int n = g_cnt[e];
    int mbase = blockIdx.y * 64;
    if (mbase >= n) return;
    int off = g_off[e];
    int nbase = blockIdx.z * 64;

    uint32_t sb = smem_u32(dsm);
    int tid = threadIdx.x, wid = tid >> 5, lane = tid & 31;
    int wm = wid >> 2, wn = wid & 3;
    int g = lane >> 2, tg = lane & 3;
    int lq = lane >> 3, lr = lane & 7;
    int lmoff = ((lq & 1) * 8 + lr) * (AS * 2) + (lq >> 1) * 16;

    const float* dp = down_proj + (size_t)e * INTER * HIDDEN + nbase;

    float acc[2][2][4] = {};

    ushort_t* Bus = (ushort_t*)(dsm + E2_BF);

    e2_prefetch(tid, off, mbase, n, sb, dp, 0, 0);

    for (int it = 0; it < INTER / 32; it++) {
        int b = it & 1;
        CP_WAIT0();
        __syncthreads();
        if (it + 1 < INTER / 32)
            e2_prefetch(tid, off, mbase, n, sb, dp, (it + 1) * 32, b ^ 1);

        // ---- convert raw B -> interleaved ----
        {
            const float* rawB = (const float*)(dsm + E2_RAW + b * 8704);
            int nn = tid & 63, kg = tid >> 6;
            #pragma unroll
            for (int kpi = 0; kpi < 4; kpi++) {
                int kp = kpi * 4 + kg;
                int k = kp * 2;
                uint32_t hi, lo;
                split2(rawB[k * RS + nn], rawB[(k + 1) * RS + nn], hi, lo);
                *(uint2*)&Bus[kp * BW + nn * 4] = make_uint2(hi, lo);
            }
        }
        __syncthreads();

        uint32_t Ah_base = sb + E2_A + b * 10240 + (wm * 32) * 80 + lmoff;
        #pragma unroll
        for (int kk = 0; kk < 32; kk += 16) {
            uint32_t ah[2][4], al[2][4];
            #pragma unroll
            for (int mf = 0; mf < 2; mf++) {
                uint32_t aaddr = Ah_base + mf * (16 * 80) + kk * 2;
                ldsm4(ah[mf], aaddr);
                ldsm4(al[mf], aaddr + 5120);
            }
            int kp0 = (kk >> 1) + tg;
            uint32_t bh[2][2], bl[2][2];
            #pragma unroll
            for (int nf = 0; nf < 2; nf++) {
                int ni = (wn * 16 + nf * 8 + g) * 4;
                uint2 v0 = *(const uint2*)&Bus[kp0 * BW + ni];
                uint2 v1 = *(const uint2*)&Bus[(kp0 + 4) * BW + ni];
                bh[nf][0] = v0.x; bh[nf][1] = v1.x;
                bl[nf][0] = v0.y; bl[nf][1] = v1.y;
            }
            #pragma unroll
            for (int mf = 0; mf < 2; mf++)
            #pragma unroll
            for (int nf = 0; nf < 2; nf++) {
                mma16816(acc[mf][nf], ah[mf], bh[nf]);
                mma16816(acc[mf][nf], ah[mf], bl[nf]);
                mma16816(acc[mf][nf], al[mf], bh[nf]);
            }
        }
    }

    // ---- epilogue: raw per-pair output rows ----
    #pragma unroll
    for (int mf = 0; mf < 2; mf++) {
        #pragma unroll
        for (int half = 0; half < 2; half++) {
            int m = mbase + wm * 32 + mf * 16 + g + half * 8;
            if (m >= n) continue;
            float* orow = g_eout + (size_t)(off + m) * HIDDEN + nbase;
            #pragma unroll
            for (int nf = 0; nf < 2; nf++) {
                int col = wn * 16 + nf * 8 + 2 * tg;
                float2 v = make_float2(acc[mf][nf][half * 2], acc[mf][nf][half * 2 + 1]);
                *(float2*)&orow[col] = v;
            }
        }
    }
}

// ================= launch =================
extern "C" void kernel_launch(void* const* d_in, const int* in_sizes, int n_in,
                              void* d_out, int out_size) {
    const float* x  = (const float*)d_in[0];
    const float* gw = (const float*)d_in[1];
    const float* gp = (const float*)d_in[2];
    const float* up = (const float*)d_in[3];
    const float* dp = (const float*)d_in[4];
    float* y = (float*)d_out;

    int T = in_sizes[0] / HIDDEN;
    int nTot = T * HIDDEN;

    static bool attr_done = false;
    if (!attr_done) {
        cudaFuncSetAttribute(e1_kernel, cudaFuncAttributeMaxDynamicSharedMemorySize, E1_SMEM);
        cudaFuncSetAttribute(e2_kernel, cudaFuncAttributeMaxDynamicSharedMemorySize, E2_SMEM);
        attr_done = true;
    }

    prep_x_kernel<<<(nTot / 4 + 255) / 256, 256>>>(x, nTot);
    router_kernel<<<T, 128>>>(x, gw);
    build_kernel<<<1, NE>>>(T);

    dim3 g1(NE, (T + 63) / 64, INTER / 64);    // (32, 8, 12)
    e1_kernel<<<g1, 256, E1_SMEM>>>(gp, up);

    dim3 g2(NE, (T + 63) / 64, HIDDEN / 64);   // (32, 8, 32)
    e2_kernel<<<g2, 256, E2_SMEM>>>(dp);

    combine_kernel<<<T, 256>>>(y);
}

// round 6
// speedup vs baseline: 1.0047x; 1.0047x over previous
#include <cuda_runtime.h>
#include <cuda_bf16.h>
#include <math.h>
#include <stdint.h>

#define HIDDEN 2048
#define INTER  768
#define NE     32
#define TOPK   8
#define MAXT   512
#define MAXP   (MAXT * TOPK)

typedef unsigned short ushort_t;

// ---- scratch (device globals) ----
__device__ float g_topw[MAXP];
__device__ int   g_topi[MAXP];
__device__ int   g_cnt[NE];
__device__ int   g_off[NE];
__device__ int   g_pt[MAXP];
__device__ int   g_t2p[MAXP];
__device__ ushort_t g_x_hi[(size_t)MAXT * HIDDEN];
__device__ ushort_t g_x_lo[(size_t)MAXT * HIDDEN];
__device__ ushort_t g_act_hi[(size_t)MAXP * INTER];
__device__ ushort_t g_act_lo[(size_t)MAXP * INTER];
__device__ float g_eout[(size_t)MAXP * HIDDEN];

// ================= helpers =================
__device__ __forceinline__ uint32_t smem_u32(const void* p) {
    uint32_t a;
    asm("{ .reg .u64 t; cvta.to.shared.u64 t, %1; cvt.u32.u64 %0, t; }" : "=r"(a) : "l"(p));
    return a;
}
__device__ __forceinline__ void cpa16(uint32_t dst, const void* src) {
    asm volatile("cp.async.ca.shared.global [%0], [%1], 16;" :: "r"(dst), "l"(src));
}
__device__ __forceinline__ void cpa8z(uint32_t dst, const void* src, int zf) {
    asm volatile("cp.async.ca.shared.global [%0], [%1], 8, %2;" :: "r"(dst), "l"(src), "r"(zf));
}
#define CP_COMMIT() asm volatile("cp.async.commit_group;" ::: "memory")
#define CP_WAIT0()  asm volatile("cp.async.wait_group 0;" ::: "memory")
#define CP_WAIT1()  asm volatile("cp.async.wait_group 1;" ::: "memory")

__device__ __forceinline__ void ldsm4(uint32_t* r, uint32_t addr) {
    asm volatile("ldmatrix.sync.aligned.m8n8.x4.shared.b16 {%0,%1,%2,%3}, [%4];"
        : "=r"(r[0]), "=r"(r[1]), "=r"(r[2]), "=r"(r[3]) : "r"(addr));
}

__device__ __forceinline__ unsigned short bfh(float v) { return __bfloat16_as_ushort(__float2bfloat16(v)); }
__device__ __forceinline__ float bff(unsigned short u) { return __bfloat162float(__ushort_as_bfloat16(u)); }
__device__ __forceinline__ void split2(float a, float b, uint32_t& hi, uint32_t& lo) {
    unsigned short ha = bfh(a), hb = bfh(b);
    float ra = a - bff(ha), rb = b - bff(hb);
    hi = (uint32_t)ha | ((uint32_t)hb << 16);
    lo = (uint32_t)bfh(ra) | ((uint32_t)bfh(rb) << 16);
}
__device__ __forceinline__ void mma16816(float* c, const uint32_t* a, const uint32_t* b) {
    asm volatile(
        "mma.sync.aligned.m16n8k16.row.col.f32.bf16.bf16.f32 "
        "{%0,%1,%2,%3}, {%4,%5,%6,%7}, {%8,%9}, {%0,%1,%2,%3};"
        : "+f"(c[0]), "+f"(c[1]), "+f"(c[2]), "+f"(c[3])
        : "r"(a[0]), "r"(a[1]), "r"(a[2]), "r"(a[3]), "r"(b[0]), "r"(b[1]));
}

#define AS 40     // A smem row stride (ushorts); 80B rows
#define BW 272    // e1 B interleaved kp-row stride (ushorts)
#define RS 68     // e1 raw fp32 row stride (floats)
#define BW2 528   // e2 B interleaved kp-row stride (ushorts), N=128
#define RS2 132   // e2 raw fp32 row stride (floats)

// ================= small kernels =================
__global__ void prep_x_kernel(const float* __restrict__ x, int nTot) {
    int i = (blockIdx.x * 256 + threadIdx.x) * 4;
    if (i < nTot) {
        float4 v = *(const float4*)(x + i);
        uint2 H, L;
        split2(v.x, v.y, H.x, L.x);
        split2(v.z, v.w, H.y, L.y);
        *(uint2*)&g_x_hi[i] = H;
        *(uint2*)&g_x_lo[i] = L;
    }
}

__global__ void router_kernel(const float* __restrict__ x, const float* __restrict__ gw) {
    int t = blockIdx.x;
    __shared__ float xs[HIDDEN];
    __shared__ float logits[NE];
    int tid = threadIdx.x;
    for (int i = tid; i < HIDDEN; i += 128) xs[i] = x[(size_t)t * HIDDEN + i];
    __syncthreads();
    int warp = tid >> 5, lane = tid & 31;
    for (int e8 = 0; e8 < 8; e8++) {
        int e = warp * 8 + e8;
        const float* w = gw + (size_t)e * HIDDEN;
        float s = 0.f;
        for (int h = lane; h < HIDDEN; h += 32) s += xs[h] * w[h];
        #pragma unroll
        for (int o = 16; o; o >>= 1) s += __shfl_xor_sync(0xffffffffu, s, o);
        if (lane == 0) logits[e] = s;
    }
    __syncthreads();
    if (tid == 0) {
        float mx = -1e30f;
        for (int e = 0; e < NE; e++) mx = fmaxf(mx, logits[e]);
        float p[NE];
        for (int e = 0; e < NE; e++) p[e] = expf(logits[e] - mx);
        bool used[NE] = {};
        float wsum = 0.f; int idx[TOPK]; float wv[TOPK];
        for (int k = 0; k < TOPK; k++) {
            float best = -1.f; int bi = 0;
            for (int e = 0; e < NE; e++)
                if (!used[e] && p[e] > best) { best = p[e]; bi = e; }
            used[bi] = true; idx[k] = bi; wv[k] = best; wsum += best;
        }
        float inv = 1.f / wsum;
        for (int k = 0; k < TOPK; k++) {
            g_topi[t * TOPK + k] = idx[k];
            g_topw[t * TOPK + k] = wv[k] * inv;
        }
    }
}

__global__ void build_kernel(int T) {
    __shared__ int cnts[NE];
    int e = threadIdx.x;
    int np = T * TOPK;
    int c = 0;
    for (int p = 0; p < np; p++) if (g_topi[p] == e) c++;
    cnts[e] = c;
    __syncthreads();
    int off = 0;
    for (int i = 0; i < e; i++) off += cnts[i];
    g_off[e] = off;
    g_cnt[e] = c;
    int j = off;
    for (int p = 0; p < np; p++)
        if (g_topi[p] == e) { g_pt[j] = p >> 3; g_t2p[p] = j; j++; }
}

__global__ void combine_kernel(float* __restrict__ y) {
    int t = blockIdx.x, tid = threadIdx.x;
    __shared__ int   pj[TOPK];
    __shared__ float pw[TOPK];
    if (tid < TOPK) { pj[tid] = g_t2p[t * TOPK + tid]; pw[tid] = g_topw[t * TOPK + tid]; }
    __syncthreads();
    #pragma unroll
    for (int h = 0; h < 2; h++) {
        int c = h * 1024 + tid * 4;
        float4 acc = make_float4(0.f, 0.f, 0.f, 0.f);
        #pragma unroll
        for (int k = 0; k < TOPK; k++) {
            const float4 v = *(const float4*)(g_eout + (size_t)pj[k] * HIDDEN + c);
            float w = pw[k];
            acc.x += w * v.x; acc.y += w * v.y; acc.z += w * v.z; acc.w += w * v.w;
        }
        *(float4*)(y + (size_t)t * HIDDEN + c) = acc;
    }
}

// ================= E1 =================
// smem: toks @0 (256B) | A x3 @256 (3 x 10240) | raw x2 @30976 (2 x (G8704+U8704))
//       | bfW x2 @65792 (2 x (G8704+U8704))
#define E1_A    256
#define E1_RAW  30976
#define E1_BFW  65792
#define E1_SMEM 100608
#define E1_NIT  (HIDDEN / 32)

extern __shared__ __align__(16) char dsm[];

__device__ __forceinline__ void e1_prefetch(int tid, const int* toks, uint32_t sb,
                                            const float* gp, const float* up_,
                                            int k0, int braw, int b3) {
    uint32_t Abase = sb + E1_A + b3 * 10240;
    #pragma unroll
    for (int q = 0; q < 2; q++) {
        int lin = q * 256 + tid;
        int m = lin >> 3, c = lin & 7;
        int t = toks[m];
        int zf = (t >= 0) ? 8 : 0;
        size_t so = (size_t)(t >= 0 ? t : 0) * HIDDEN + k0 + c * 4;
        uint32_t d = Abase + m * 80 + c * 8;
        cpa8z(d, g_x_hi + so, zf);
        cpa8z(d + 5120, g_x_lo + so, zf);
    }
    uint32_t Rbase = sb + E1_RAW + braw * 17408;
    #pragma unroll
    for (int q = 0; q < 2; q++) {
        int lin = q * 256 + tid;
        int k = lin >> 4, n4 = lin & 15;
        uint32_t d = Rbase + k * 272 + n4 * 16;
        size_t so = (size_t)(k0 + k) * INTER + n4 * 4;
        cpa16(d, gp + so);
        cpa16(d + 8704, up_ + so);
    }
    CP_COMMIT();
}

__device__ __forceinline__ void e1_convert(int tid, const char* dsm_, int braw, int bbf) {
    const float* rawG = (const float*)(dsm_ + E1_RAW + braw * 17408);
    const float* rawU = rawG + 2176;
    ushort_t* Gus = (ushort_t*)(dsm_ + E1_BFW + bbf * 17408);
    ushort_t* Uus = Gus + 4352;
    int nn = tid & 63, kg = tid >> 6;
    #pragma unroll
    for (int kpi = 0; kpi < 4; kpi++) {
        int kp = kpi * 4 + kg;
        int k = kp * 2;
        int wi = kp * BW + nn * 4;
        uint32_t hi, lo;
        split2(rawG[k * RS + nn], rawG[(k + 1) * RS + nn], hi, lo);
        *(uint2*)&Gus[wi] = make_uint2(hi, lo);
        split2(rawU[k * RS + nn], rawU[(k + 1) * RS + nn], hi, lo);
        *(uint2*)&Uus[wi] = make_uint2(hi, lo);
    }
}

__global__ __launch_bounds__(256, 2)
void e1_kernel(const float* __restrict__ gate_proj,
               const float* __restrict__ up_proj) {
    int e = blockIdx.x;
    int n = g_cnt[e];
    int mbase = blockIdx.y * 64;
    if (mbase >= n) return;
    int off = g_off[e];
    int nbase = blockIdx.z * 64;

    uint32_t sb = smem_u32(dsm);
    int tid = threadIdx.x, wid = tid >> 5, lane = tid & 31;
    int* toks = (int*)dsm;
    if (tid < 64) { int m = mbase + tid; toks[tid] = (m < n) ? g_pt[off + m] : -1; }
    __syncthreads();

    const float* gp  = gate_proj + (size_t)e * HIDDEN * INTER + nbase;
    const float* up_ = up_proj   + (size_t)e * HIDDEN * INTER + nbase;

    int wm = wid >> 2, wn = wid & 3;
    int g = lane >> 2, tg = lane & 3;
    int lq = lane >> 3, lr = lane & 7;
    int lmoff = ((lq & 1) * 8 + lr) * (AS * 2) + (lq >> 1) * 16;

    float accg[2][2][4] = {};
    float accu[2][2][4] = {};

    // prologue: prefetch 0, 1; convert 0
    e1_prefetch(tid, toks, sb, gp, up_, 0, 0, 0);
    e1_prefetch(tid, toks, sb, gp, up_, 32, 1, 1);
    CP_WAIT1();
    __syncthreads();
    e1_convert(tid, dsm, 0, 0);
    __syncthreads();

    for (int it = 0; it < E1_NIT; it++) {
        int b2 = it & 1;
        int b3 = it % 3;

        // ---- MMA phase: issue all HMMAs into the tensor queue ----
        const ushort_t* Gus = (const ushort_t*)(dsm + E1_BFW + b2 * 17408);
        const ushort_t* Uus = Gus + 4352;
        uint32_t Ah_base = sb + E1_A + b3 * 10240 + (wm * 32) * 80 + lmoff;
        #pragma unroll
        for (int kk = 0; kk < 32; kk += 16) {
            uint32_t ah[2][4], al[2][4];
            #pragma unroll
            for (int mf = 0; mf < 2; mf++) {
                uint32_t aaddr = Ah_base + mf * (16 * 80) + kk * 2;
                ldsm4(ah[mf], aaddr);
                ldsm4(al[mf], aaddr + 5120);
            }
            int kp0 = (kk >> 1) + tg;
            {
                uint32_t bh[2][2], bl[2][2];
                #pragma unroll
                for (int nf = 0; nf < 2; nf++) {
                    int ni = (wn * 16 + nf * 8 + g) * 4;
                    uint2 v0 = *(const uint2*)&Gus[kp0 * BW + ni];
                    uint2 v1 = *(const uint2*)&Gus[(kp0 + 4) * BW + ni];
                    bh[nf][0] = v0.x; bh[nf][1] = v1.x;
                    bl[nf][0] = v0.y; bl[nf][1] = v1.y;
                }
                #pragma unroll
                for (int mf = 0; mf < 2; mf++)
                #pragma unroll
                for (int nf = 0; nf < 2; nf++) {
                    mma16816(accg[mf][nf], ah[mf], bh[nf]);
                    mma16816(accg[mf][nf], ah[mf], bl[nf]);
                    mma16816(accg[mf][nf], al[mf], bh[nf]);
                }
            }
            {
                uint32_t bh[2][2], bl[2][2];
                #pragma unroll
                for (int nf = 0; nf < 2; nf++) {
                    int ni = (wn * 16 + nf * 8 + g) * 4;
                    uint2 v0 = *(const uint2*)&Uus[kp0 * BW + ni];
                    uint2 v1 = *(const uint2*)&Uus[(kp0 + 4) * BW + ni];
                    bh[nf][0] = v0.x; bh[nf][1] = v1.x;
                    bl[nf][0] = v0.y; bl[nf][1] = v1.y;
                }
                #pragma unroll
                for (int mf = 0; mf < 2; mf++)
                #pragma unroll
                for (int nf = 0; nf < 2; nf++) {
                    mma16816(accu[mf][nf], ah[mf], bh[nf]);
                    mma16816(accu[mf][nf], ah[mf], bl[nf]);
                    mma16816(accu[mf][nf], al[mf], bh[nf]);
                }
            }
        }

        // ---- prefetch(it+2) + wait ----
        if (it + 2 < E1_NIT) {
            e1_prefetch(tid, toks, sb, gp, up_, (it + 2) * 32, it & 1, (it + 2) % 3);
            CP_WAIT1();
        } else if (it + 1 < E1_NIT) {
            CP_WAIT0();
        }
        __syncthreads();
        // ---- convert(it+1) overlaps tensor drain of MMA(it) ----
        if (it + 1 < E1_NIT)
            e1_convert(tid, dsm, (it + 1) & 1, (it + 1) & 1);
        __syncthreads();
    }

    // ---- epilogue: silu(g)*u -> split bf16 -> g_act ----
    #pragma unroll
    for (int mf = 0; mf < 2; mf++)
    #pragma unroll
    for (int nf = 0; nf < 2; nf++)
    #pragma unroll
    for (int i = 0; i < 4; i++) {
        int m = mbase + wm * 32 + mf * 16 + g + (i >> 1) * 8;
        if (m >= n) continue;
        int col = nbase + wn * 16 + nf * 8 + 2 * tg + (i & 1);
        float gv = accg[mf][nf][i], uv = accu[mf][nf][i];
        float a = (gv / (1.f + __expf(-gv))) * uv;
        unsigned short h = bfh(a);
        float r = a - bff(h);
        size_t ai = (size_t)(off + m) * INTER + col;
        g_act_hi[ai] = h;
        g_act_lo[ai] = bfh(r);
    }
}

// ================= E2 (M64 x N128) =================
// smem: A x3 @0 (3 x 10240) | raw x2 @30720 (2 x 16896) | bfB x2 @64512 (2 x 16896)
#define E2_A    0
#define E2_RAW  30720
#define E2_BF   64512
#define E2_SMEM 98304
#define E2_NIT  (INTER / 32)

__device__ __forceinline__ void e2_prefetch(int tid, int off, int mbase, int n, uint32_t sb,
                                            const float* dp, int k0, int braw, int b3) {
    uint32_t Abase = sb + E2_A + b3 * 10240;
    #pragma unroll
    for (int q = 0; q < 2; q++) {
        int lin = q * 256 + tid;
        int m = lin >> 3, c = lin & 7;
        bool valid = (mbase + m) < n;
        int zf = valid ? 8 : 0;
        size_t so = valid ? ((size_t)(off + mbase + m) * INTER + k0 + c * 4) : 0;
        uint32_t d = Abase + m * 80 + c * 8;
        cpa8z(d, g_act_hi + so, zf);
        cpa8z(d + 5120, g_act_lo + so, zf);
    }
    uint32_t Rbase = sb + E2_RAW + braw * 16896;
    #pragma unroll
    for (int q = 0; q < 4; q++) {
        int lin = q * 256 + tid;
        int k = lin >> 5, n4 = lin & 31;
        cpa16(Rbase + k * 528 + n4 * 16, dp + (size_t)(k0 + k) * HIDDEN + n4 * 4);
    }
    CP_COMMIT();
}

__device__ __forceinline__ void e2_convert(int tid, const char* dsm_, int braw, int bbf) {
    const float* rawB = (const float*)(dsm_ + E2_RAW + braw * 16896);
    ushort_t* Bus = (ushort_t*)(dsm_ + E2_BF + bbf * 16896);
    int nn = tid & 127, kg = tid >> 7;
    #pragma unroll
    for (int kpi = 0; kpi < 8; kpi++) {
        int kp = kpi * 2 + kg;
        int k = kp * 2;
        uint32_t hi, lo;
        split2(rawB[k * RS2 + nn], rawB[(k + 1) * RS2 + nn], hi, lo);
        *(uint2*)&Bus[kp * BW2 + nn * 4] = make_uint2(hi, lo);
    }
}

__global__ __launch_bounds__(256, 2)
void e2_kernel(const float* __restrict__ down_proj) {
    int e = blockIdx.x;
    int n = g_cnt[e];
    int mbase = blockIdx.y * 64;
    if (mbase >= n) return;
    int off = g_off[e];
    int nbase = blockIdx.z * 128;

    uint32_t sb = smem_u32(dsm);
    int tid = threadIdx.x, wid = tid >> 5, lane = tid & 31;
    int wm = wid >> 2, wn = wid & 3;      // 2 x 4 warps over 64m x 128n
    int g = lane >> 2, tg = lane & 3;
    int lq = lane >> 3, lr = lane & 7;
    int lmoff = ((lq & 1) * 8 + lr) * (AS * 2) + (lq >> 1) * 16;

    const float* dp = down_proj + (size_t)e * INTER * HIDDEN + nbase;

    float acc[2][4][4] = {};

    e2_prefetch(tid, off, mbase, n, sb, dp, 0, 0, 0);
    e2_prefetch(tid, off, mbase, n, sb, dp, 32, 1, 1);
    CP_WAIT1();
    __syncthreads();
    e2_convert(tid, dsm, 0, 0);
    __syncthreads();

    for (int it = 0; it < E2_NIT; it++) {
        int b2 = it & 1;
        int b3 = it % 3;

        const ushort_t* Bus = (const ushort_t*)(dsm + E2_BF + b2 * 16896);
        uint32_t Ah_base = sb + E2_A + b3 * 10240 + (wm * 32) * 80 + lmoff;
        #pragma unroll
        for (int kk = 0; kk < 32; kk += 16) {
            uint32_t ah[2][4], al[2][4];
            #pragma unroll
            for (int mf = 0; mf < 2; mf++) {
                uint32_t aaddr = Ah_base + mf * (16 * 80) + kk * 2;
                ldsm4(ah[mf], aaddr);
                ldsm4(al[mf], aaddr + 5120);
            }
            int kp0 = (kk >> 1) + tg;
            uint32_t bh[4][2], bl[4][2];
            #pragma unroll
            for (int nf = 0; nf < 4; nf++) {
                int ni = (wn * 32 + nf * 8 + g) * 4;
                uint2 v0 = *(const uint2*)&Bus[kp0 * BW2 + ni];
                uint2 v1 = *(const uint2*)&Bus[(kp0 + 4) * BW2 + ni];
                bh[nf][0] = v0.x; bh[nf][1] = v1.x;
                bl[nf][0] = v0.y; bl[nf][1] = v1.y;
            }
            #pragma unroll
            for (int mf = 0; mf < 2; mf++)
            #pragma unroll
            for (int nf = 0; nf < 4; nf++) {
                mma16816(acc[mf][nf], ah[mf], bh[nf]);
                mma16816(acc[mf][nf], ah[mf], bl[nf]);
                mma16816(acc[mf][nf], al[mf], bh[nf]);
            }
        }

        if (it + 2 < E2_NIT) {
            e2_prefetch(tid, off, mbase, n, sb, dp, (it + 2) * 32, it & 1, (it + 2) % 3);
            CP_WAIT1();
        } else if (it + 1 < E2_NIT) {
            CP_WAIT0();
        }
        __syncthreads();
        if (it + 1 < E2_NIT)
            e2_convert(tid, dsm, (it + 1) & 1, (it + 1) & 1);
        __syncthreads();
    }

    // ---- epilogue: raw per-pair output rows ----
    #pragma unroll
    for (int mf = 0; mf < 2; mf++) {
        #pragma unroll
        for (int half = 0; half < 2; half++) {
            int m = mbase + wm * 32 + mf * 16 + g + half * 8;
            if (m >= n) continue;
            float* orow = g_eout + (size_t)(off + m) * HIDDEN + nbase;
            #pragma unroll
            for (int nf = 0; nf < 4; nf++) {
                int col = wn * 32 + nf * 8 + 2 * tg;
                float2 v = make_float2(acc[mf][nf][half * 2], acc[mf][nf][half * 2 + 1]);
                *(float2*)&orow[col] = v;
            }
        }
    }
}

// ================= launch =================
extern "C" void kernel_launch(void* const* d_in, const int* in_sizes, int n_in,
                              void* d_out, int out_size) {
    const float* x  = (const float*)d_in[0];
    const float* gw = (const float*)d_in[1];
    const float* gp = (const float*)d_in[2];
    const float* up = (const float*)d_in[3];
    const float* dp = (const float*)d_in[4];
    float* y = (float*)d_out;

    int T = in_sizes[0] / HIDDEN;
    int nTot = T * HIDDEN;

    static bool attr_done = false;
    if (!attr_done) {
        cudaFuncSetAttribute(e1_kernel, cudaFuncAttributeMaxDynamicSharedMemorySize, E1_SMEM);
        cudaFuncSetAttribute(e2_kernel, cudaFuncAttributeMaxDynamicSharedMemorySize, E2_SMEM);
        attr_done = true;
    }

    prep_x_kernel<<<(nTot / 4 + 255) / 256, 256>>>(x, nTot);
    router_kernel<<<T, 128>>>(x, gw);
    build_kernel<<<1, NE>>>(T);

    dim3 g1(NE, (T + 63) / 64, INTER / 64);    // (32, 8, 12)
    e1_kernel<<<g1, 256, E1_SMEM>>>(gp, up);

    dim3 g2(NE, (T + 63) / 64, HIDDEN / 128);  // (32, 8, 16)
    e2_kernel<<<g2, 256, E2_SMEM>>>(dp);

    combine_kernel<<<T, 256>>>(y);
}

// round 7
// speedup vs baseline: 1.5585x; 1.5512x over previous
#include <cuda_runtime.h>
#include <cuda_bf16.h>
#include <math.h>
#include <stdint.h>

#define HIDDEN 2048
#define INTER  768
#define NE     32
#define TOPK   8
#define MAXT   512
#define MAXP   (MAXT * TOPK)

typedef unsigned short ushort_t;

// ---- scratch (device globals) ----
__device__ float g_topw[MAXP];
__device__ int   g_topi[MAXP];
__device__ int   g_cnt[NE];
__device__ int   g_off[NE];
__device__ int   g_pt[MAXP];
__device__ int   g_t2p[MAXP];
__device__ ushort_t g_x_hi[(size_t)MAXT * HIDDEN];
__device__ ushort_t g_x_lo[(size_t)MAXT * HIDDEN];
__device__ ushort_t g_act_hi[(size_t)MAXP * INTER];
__device__ ushort_t g_act_lo[(size_t)MAXP * INTER];
__device__ float g_eout[(size_t)MAXP * HIDDEN];

// ================= helpers =================
__device__ __forceinline__ uint32_t smem_u32(const void* p) {
    uint32_t a;
    asm("{ .reg .u64 t; cvta.to.shared.u64 t, %1; cvt.u32.u64 %0, t; }" : "=r"(a) : "l"(p));
    return a;
}
__device__ __forceinline__ void cpa16(uint32_t dst, const void* src) {
    asm volatile("cp.async.ca.shared.global [%0], [%1], 16;" :: "r"(dst), "l"(src));
}
__device__ __forceinline__ void cpa8z(uint32_t dst, const void* src, int zf) {
    asm volatile("cp.async.ca.shared.global [%0], [%1], 8, %2;" :: "r"(dst), "l"(src), "r"(zf));
}
#define CP_COMMIT() asm volatile("cp.async.commit_group;" ::: "memory")
#define CP_WAIT0()  asm volatile("cp.async.wait_group 0;" ::: "memory")

__device__ __forceinline__ void ldsm4(uint32_t* r, uint32_t addr) {
    asm volatile("ldmatrix.sync.aligned.m8n8.x4.shared.b16 {%0,%1,%2,%3}, [%4];"
        : "=r"(r[0]), "=r"(r[1]), "=r"(r[2]), "=r"(r[3]) : "r"(addr));
}

__device__ __forceinline__ unsigned short bfh(float v) { return __bfloat16_as_ushort(__float2bfloat16(v)); }

// cheap split: hi = truncated top-16 bits (exact residual), lo = RN-bf16 of residual
__device__ __forceinline__ void split2t(float a, float b, uint32_t& hi, uint32_t& lo) {
    uint32_t ua = __float_as_uint(a), ub = __float_as_uint(b);
    hi = __byte_perm(ua, ub, 0x7632);               // (b_hi16<<16) | a_hi16
    float ra = a - __uint_as_float(ua & 0xFFFF0000u);
    float rb = b - __uint_as_float(ub & 0xFFFF0000u);
    asm("cvt.rn.bf16x2.f32 %0, %1, %2;" : "=r"(lo) : "f"(rb), "f"(ra));
}

__device__ __forceinline__ void mma16816(float* c, const uint32_t* a, const uint32_t* b) {
    asm volatile(
        "mma.sync.aligned.m16n8k16.row.col.f32.bf16.bf16.f32 "
        "{%0,%1,%2,%3}, {%4,%5,%6,%7}, {%8,%9}, {%0,%1,%2,%3};"
        : "+f"(c[0]), "+f"(c[1]), "+f"(c[2]), "+f"(c[3])
        : "r"(a[0]), "r"(a[1]), "r"(a[2]), "r"(a[3]), "r"(b[0]), "r"(b[1]));
}

#define AS 40     // A smem row stride (ushorts); 80B rows
#define BW 272    // e1 B interleaved kp-row stride (ushorts)
#define RS 68     // e1 raw fp32 row stride (floats)
#define BW2 528   // e2 B interleaved kp-row stride (ushorts), N=128
#define RS2 132   // e2 raw fp32 row stride (floats)

// ================= small kernels =================
__global__ void prep_x_kernel(const float* __restrict__ x, int nTot) {
    int i = (blockIdx.x * 256 + threadIdx.x) * 4;
    if (i < nTot) {
        float4 v = *(const float4*)(x + i);
        uint2 H, L;
        split2t(v.x, v.y, H.x, L.x);
        split2t(v.z, v.w, H.y, L.y);
        *(uint2*)&g_x_hi[i] = H;
        *(uint2*)&g_x_lo[i] = L;
    }
}

__global__ void router_kernel(const float* __restrict__ x, const float* __restrict__ gw) {
    int t = blockIdx.x;
    __shared__ float xs[HIDDEN];
    __shared__ float logits[NE];
    int tid = threadIdx.x;
    for (int i = tid; i < HIDDEN; i += 128) xs[i] = x[(size_t)t * HIDDEN + i];
    __syncthreads();
    int warp = tid >> 5, lane = tid & 31;
    for (int e8 = 0; e8 < 8; e8++) {
        int e = warp * 8 + e8;
        const float* w = gw + (size_t)e * HIDDEN;
        float s = 0.f;
        for (int h = lane; h < HIDDEN; h += 32) s += xs[h] * w[h];
        #pragma unroll
        for (int o = 16; o; o >>= 1) s += __shfl_xor_sync(0xffffffffu, s, o);
        if (lane == 0) logits[e] = s;
    }
    __syncthreads();
    if (tid == 0) {
        float mx = -1e30f;
        for (int e = 0; e < NE; e++) mx = fmaxf(mx, logits[e]);
        float p[NE];
        for (int e = 0; e < NE; e++) p[e] = expf(logits[e] - mx);
        bool used[NE] = {};
        float wsum = 0.f; int idx[TOPK]; float wv[TOPK];
        for (int k = 0; k < TOPK; k++) {
            float best = -1.f; int bi = 0;
            for (int e = 0; e < NE; e++)
                if (!used[e] && p[e] > best) { best = p[e]; bi = e; }
            used[bi] = true; idx[k] = bi; wv[k] = best; wsum += best;
        }
        float inv = 1.f / wsum;
        for (int k = 0; k < TOPK; k++) {
            g_topi[t * TOPK + k] = idx[k];
            g_topw[t * TOPK + k] = wv[k] * inv;
        }
    }
}

// parallel pair-list build; within-expert order arbitrary but output-invariant
__global__ void build_kernel(int T) {
    __shared__ int cnt[NE], cur[NE];
    int tid = threadIdx.x;
    int np = T * TOPK;
    if (tid < NE) cnt[tid] = 0;
    __syncthreads();
    for (int p = tid; p < np; p += blockDim.x) atomicAdd(&cnt[g_topi[p]], 1);
    __syncthreads();
    if (tid == 0) {
        int off = 0;
        for (int e = 0; e < NE; e++) {
            g_off[e] = off; g_cnt[e] = cnt[e]; cur[e] = off; off += cnt[e];
        }
    }
    __syncthreads();
    for (int p = tid; p < np; p += blockDim.x) {
        int e = g_topi[p];
        int j = atomicAdd(&cur[e], 1);
        g_pt[j] = p >> 3;
        g_t2p[p] = j;
    }
}

__global__ void combine_kernel(float* __restrict__ y) {
    int t = blockIdx.x, tid = threadIdx.x;
    __shared__ int   pj[TOPK];
    __shared__ float pw[TOPK];
    if (tid < TOPK) { pj[tid] = g_t2p[t * TOPK + tid]; pw[tid] = g_topw[t * TOPK + tid]; }
    __syncthreads();
    #pragma unroll
    for (int h = 0; h < 2; h++) {
        int c = h * 1024 + tid * 4;
        float4 acc = make_float4(0.f, 0.f, 0.f, 0.f);
        #pragma unroll
        for (int k = 0; k < TOPK; k++) {
            const float4 v = *(const float4*)(g_eout + (size_t)pj[k] * HIDDEN + c);
            float w = pw[k];
            acc.x += w * v.x; acc.y += w * v.y; acc.z += w * v.z; acc.w += w * v.w;
        }
        *(float4*)(y + (size_t)t * HIDDEN + c) = acc;
    }
}

// ================= E1 =================
// smem: toks @0 (256B) | A x2 @256 (2 x 10240) | raw x2 @20736 (2 x (G8704+U8704))
//       | bfW @55552 (G 8704 + U 8704)
#define E1_A    256
#define E1_RAW  20736
#define E1_BFW  55552
#define E1_SMEM 72960
#define E1_NIT  (HIDDEN / 32)

extern __shared__ __align__(16) char dsm[];

__device__ __forceinline__ void e1_prefetch(int tid, const int* toks, uint32_t sb,
                                            const float* gp, const float* up_,
                                            int k0, int b) {
    uint32_t Abase = sb + E1_A + b * 10240;
    #pragma unroll
    for (int q = 0; q < 2; q++) {
        int lin = q * 256 + tid;
        int m = lin >> 3, c = lin & 7;
        int t = toks[m];
        int zf = (t >= 0) ? 8 : 0;
        size_t so = (size_t)(t >= 0 ? t : 0) * HIDDEN + k0 + c * 4;
        uint32_t d = Abase + m * 80 + c * 8;
        cpa8z(d, g_x_hi + so, zf);
        cpa8z(d + 5120, g_x_lo + so, zf);
    }
    uint32_t Rbase = sb + E1_RAW + b * 17408;
    #pragma unroll
    for (int q = 0; q < 2; q++) {
        int lin = q * 256 + tid;
        int k = lin >> 4, n4 = lin & 15;
        uint32_t d = Rbase + k * 272 + n4 * 16;
        size_t so = (size_t)(k0 + k) * INTER + n4 * 4;
        cpa16(d, gp + so);
        cpa16(d + 8704, up_ + so);
    }
    CP_COMMIT();
}

__device__ __forceinline__ void e1_convert(int tid, const char* dsm_, int braw) {
    const float* rawG = (const float*)(dsm_ + E1_RAW + braw * 17408);
    const float* rawU = rawG + 2176;
    ushort_t* Gus = (ushort_t*)(dsm_ + E1_BFW);
    ushort_t* Uus = Gus + 4352;
    int nn = tid & 63, kg = tid >> 6;
    #pragma unroll
    for (int kpi = 0; kpi < 4; kpi++) {
        int kp = kpi * 4 + kg;
        int k = kp * 2;
        int wi = kp * BW + nn * 4;
        uint32_t hi, lo;
        split2t(rawG[k * RS + nn], rawG[(k + 1) * RS + nn], hi, lo);
        *(uint2*)&Gus[wi] = make_uint2(hi, lo);
        split2t(rawU[k * RS + nn], rawU[(k + 1) * RS + nn], hi, lo);
        *(uint2*)&Uus[wi] = make_uint2(hi, lo);
    }
}

__global__ __launch_bounds__(256, 2)
void e1_kernel(const float* __restrict__ gate_proj,
               const float* __restrict__ up_proj) {
    int e = blockIdx.x;
    int n = g_cnt[e];
    int mbase = blockIdx.y * 64;
    if (mbase >= n) return;
    int off = g_off[e];
    int nbase = blockIdx.z * 64;

    uint32_t sb = smem_u32(dsm);
    int tid = threadIdx.x, wid = tid >> 5, lane = tid & 31;
    int* toks = (int*)dsm;
    if (tid < 64) { int m = mbase + tid; toks[tid] = (m < n) ? g_pt[off + m] : -1; }
    __syncthreads();

    const float* gp  = gate_proj + (size_t)e * HIDDEN * INTER + nbase;
    const float* up_ = up_proj   + (size_t)e * HIDDEN * INTER + nbase;

    int wm = wid >> 2, wn = wid & 3;
    int g = lane >> 2, tg = lane & 3;
    int lq = lane >> 3, lr = lane & 7;
    int lmoff = ((lq & 1) * 8 + lr) * (AS * 2) + (lq >> 1) * 16;

    float accg[2][2][4] = {};
    float accu[2][2][4] = {};

    ushort_t* Gus = (ushort_t*)(dsm + E1_BFW);
    ushort_t* Uus = Gus + 4352;

    e1_prefetch(tid, toks, sb, gp, up_, 0, 0);

    for (int it = 0; it < E1_NIT; it++) {
        int b = it & 1;
        CP_WAIT0();
        __syncthreads();
        if (it + 1 < E1_NIT)
            e1_prefetch(tid, toks, sb, gp, up_, (it + 1) * 32, b ^ 1);

        e1_convert(tid, dsm, b);
        __syncthreads();

        uint32_t Ah_base = sb + E1_A + b * 10240 + (wm * 32) * 80 + lmoff;
        #pragma unroll
        for (int kk = 0; kk < 32; kk += 16) {
            uint32_t ah[2][4], al[2][4];
            #pragma unroll
            for (int mf = 0; mf < 2; mf++) {
                uint32_t aaddr = Ah_base + mf * (16 * 80) + kk * 2;
                ldsm4(ah[mf], aaddr);
                ldsm4(al[mf], aaddr + 5120);
            }
            int kp0 = (kk >> 1) + tg;
            {
                uint32_t bh[2][2], bl[2][2];
                #pragma unroll
                for (int nf = 0; nf < 2; nf++) {
                    int ni = (wn * 16 + nf * 8 + g) * 4;
                    uint2 v0 = *(const uint2*)&Gus[kp0 * BW + ni];
                    uint2 v1 = *(const uint2*)&Gus[(kp0 + 4) * BW + ni];
                    bh[nf][0] = v0.x; bh[nf][1] = v1.x;
                    bl[nf][0] = v0.y; bl[nf][1] = v1.y;
                }
                #pragma unroll
                for (int mf = 0; mf < 2; mf++)
                #pragma unroll
                for (int nf = 0; nf < 2; nf++) {
                    mma16816(accg[mf][nf], ah[mf], bh[nf]);
                    mma16816(accg[mf][nf], ah[mf], bl[nf]);
                    mma16816(accg[mf][nf], al[mf], bh[nf]);
                }
            }
            {
                uint32_t bh[2][2], bl[2][2];
                #pragma unroll
                for (int nf = 0; nf < 2; nf++) {
                    int ni = (wn * 16 + nf * 8 + g) * 4;
                    uint2 v0 = *(const uint2*)&Uus[kp0 * BW + ni];
                    uint2 v1 = *(const uint2*)&Uus[(kp0 + 4) * BW + ni];
                    bh[nf][0] = v0.x; bh[nf][1] = v1.x;
                    bl[nf][0] = v0.y; bl[nf][1] = v1.y;
                }
                #pragma unroll
                for (int mf = 0; mf < 2; mf++)
                #pragma unroll
                for (int nf = 0; nf < 2; nf++) {
                    mma16816(accu[mf][nf], ah[mf], bh[nf]);
                    mma16816(accu[mf][nf], ah[mf], bl[nf]);
                    mma16816(accu[mf][nf], al[mf], bh[nf]);
                }
            }
        }
        __syncthreads();
    }

    // ---- epilogue: silu(g)*u -> split bf16 -> g_act ----
    #pragma unroll
    for (int mf = 0; mf < 2; mf++)
    #pragma unroll
    for (int nf = 0; nf < 2; nf++)
    #pragma unroll
    for (int i = 0; i < 4; i++) {
        int m = mbase + wm * 32 + mf * 16 + g + (i >> 1) * 8;
        if (m >= n) continue;
        int col = nbase + wn * 16 + nf * 8 + 2 * tg + (i & 1);
        float gv = accg[mf][nf][i], uv = accu[mf][nf][i];
        float a = (gv / (1.f + __expf(-gv))) * uv;
        uint32_t ua = __float_as_uint(a);
        float r = a - __uint_as_float(ua & 0xFFFF0000u);
        size_t ai = (size_t)(off + m) * INTER + col;
        g_act_hi[ai] = (ushort_t)(ua >> 16);
        g_act_lo[ai] = bfh(r);
    }
}

// ================= E2 (M64 x N128) =================
// smem: A x2 @0 (2 x 10240) | raw x2 @20480 (2 x 16896) | bfB @54272 (16896)
#define E2_A    0
#define E2_RAW  20480
#define E2_BF   54272
#define E2_SMEM 71168
#define E2_NIT  (INTER / 32)

__device__ __forceinline__ void e2_prefetch(int tid, int off, int mbase, int n, uint32_t sb,
                                            const float* dp, int k0, int b) {
    uint32_t Abase = sb + E2_A + b * 10240;
    #pragma unroll
    for (int q = 0; q < 2; q++) {
        int lin = q * 256 + tid;
        int m = lin >> 3, c = lin & 7;
        bool valid = (mbase + m) < n;
        int zf = valid ? 8 : 0;
        size_t so = valid ? ((size_t)(off + mbase + m) * INTER + k0 + c * 4) : 0;
        uint32_t d = Abase + m * 80 + c * 8;
        cpa8z(d, g_act_hi + so, zf);
        cpa8z(d + 5120, g_act_lo + so, zf);
    }
    uint32_t Rbase = sb + E2_RAW + b * 16896;
    #pragma unroll
    for (int q = 0; q < 4; q++) {
        int lin = q * 256 + tid;
        int k = lin >> 5, n4 = lin & 31;
        cpa16(Rbase + k * 528 + n4 * 16, dp + (size_t)(k0 + k) * HIDDEN + n4 * 4);
    }
    CP_COMMIT();
}

__device__ __forceinline__ void e2_convert(int tid, const char* dsm_, int braw) {
    const float* rawB = (const float*)(dsm_ + E2_RAW + braw * 16896);
    ushort_t* Bus = (ushort_t*)(dsm_ + E2_BF);
    int nn = tid & 127, kg = tid >> 7;
    #pragma unroll
    for (int kpi = 0; kpi < 8; kpi++) {
        int kp = kpi * 2 + kg;
        int k = kp * 2;
        uint32_t hi, lo;
        split2t(rawB[k * RS2 + nn], rawB[(k + 1) * RS2 + nn], hi, lo);
        *(uint2*)&Bus[kp * BW2 + nn * 4] = make_uint2(hi, lo);
    }
}

__global__ __launch_bounds__(256, 2)
void e2_kernel(const float* __restrict__ down_proj) {
    int e = blockIdx.x;
    int n = g_cnt[e];
    int mbase = blockIdx.y * 64;
    if (mbase >= n) return;
    int off = g_off[e];
    int nbase = blockIdx.z * 128;

    uint32_t sb = smem_u32(dsm);
    int tid = threadIdx.x, wid = tid >> 5, lane = tid & 31;
    int wm = wid >> 2, wn = wid & 3;
    int g = lane >> 2, tg = lane & 3;
    int lq = lane >> 3, lr = lane & 7;
    int lmoff = ((lq & 1) * 8 + lr) * (AS * 2) + (lq >> 1) * 16;

    const float* dp = down_proj + (size_t)e * INTER * HIDDEN + nbase;

    float acc[2][4][4] = {};
    ushort_t* Bus = (ushort_t*)(dsm + E2_BF);

    e2_prefetch(tid, off, mbase, n, sb, dp, 0, 0);

    for (int it = 0; it < E2_NIT; it++) {
        int b = it & 1;
        CP_WAIT0();
        __syncthreads();
        if (it + 1 < E2_NIT)
            e2_prefetch(tid, off, mbase, n, sb, dp, (it + 1) * 32, b ^ 1);

        e2_convert(tid, dsm, b);
        __syncthreads();

        uint32_t Ah_base = sb + E2_A + b * 10240 + (wm * 32) * 80 + lmoff;
        #pragma unroll
        for (int kk = 0; kk < 32; kk += 16) {
            uint32_t ah[2][4], al[2][4];
            #pragma unroll
            for (int mf = 0; mf < 2; mf++) {
                uint32_t aaddr = Ah_base + mf * (16 * 80) + kk * 2;
                ldsm4(ah[mf], aaddr);
                ldsm4(al[mf], aaddr + 5120);
            }
            int kp0 = (kk >> 1) + tg;
            uint32_t bh[4][2], bl[4][2];
            #pragma unroll
            for (int nf = 0; nf < 4; nf++) {
                int ni = (wn * 32 + nf * 8 + g) * 4;
                uint2 v0 = *(const uint2*)&Bus[kp0 * BW2 + ni];
                uint2 v1 = *(const uint2*)&Bus[(kp0 + 4) * BW2 + ni];
                bh[nf][0] = v0.x; bh[nf][1] = v1.x;
                bl[nf][0] = v0.y; bl[nf][1] = v1.y;
            }
            #pragma unroll
            for (int mf = 0; mf < 2; mf++)
            #pragma unroll
            for (int nf = 0; nf < 4; nf++) {
                mma16816(acc[mf][nf], ah[mf], bh[nf]);
                mma16816(acc[mf][nf], ah[mf], bl[nf]);
                mma16816(acc[mf][nf], al[mf], bh[nf]);
            }
        }
        __syncthreads();
    }

    // ---- epilogue: raw per-pair output rows ----
    #pragma unroll
    for (int mf = 0; mf < 2; mf++) {
        #pragma unroll
        for (int half = 0; half < 2; half++) {
            int m = mbase + wm * 32 + mf * 16 + g + half * 8;
            if (m >= n) continue;
            float* orow = g_eout + (size_t)(off + m) * HIDDEN + nbase;
            #pragma unroll
            for (int nf = 0; nf < 4; nf++) {
                int col = wn * 32 + nf * 8 + 2 * tg;
                float2 v = make_float2(acc[mf][nf][half * 2], acc[mf][nf][half * 2 + 1]);
                *(float2*)&orow[col] = v;
            }
        }
    }
}

// ================= launch =================
extern "C" void kernel_launch(void* const* d_in, const int* in_sizes, int n_in,
                              void* d_out, int out_size) {
    const float* x  = (const float*)d_in[0];
    const float* gw = (const float*)d_in[1];
    const float* gp = (const float*)d_in[2];
    const float* up = (const float*)d_in[3];
    const float* dp = (const float*)d_in[4];
    float* y = (float*)d_out;

    int T = in_sizes[0] / HIDDEN;
    int nTot = T * HIDDEN;

    static bool attr_done = false;
    if (!attr_done) {
        cudaFuncSetAttribute(e1_kernel, cudaFuncAttributeMaxDynamicSharedMemorySize, E1_SMEM);
        cudaFuncSetAttribute(e2_kernel, cudaFuncAttributeMaxDynamicSharedMemorySize, E2_SMEM);
        attr_done = true;
    }

    prep_x_kernel<<<(nTot / 4 + 255) / 256, 256>>>(x, nTot);
    router_kernel<<<T, 128>>>(x, gw);
    build_kernel<<<1, 512>>>(T);

    dim3 g1(NE, (T + 63) / 64, INTER / 64);    // (32, 8, 12)
    e1_kernel<<<g1, 256, E1_SMEM>>>(gp, up);

    dim3 g2(NE, (T + 63) / 64, HIDDEN / 128);  // (32, 8, 16)
    e2_kernel<<<g2, 256, E2_SMEM>>>(dp);

    combine_kernel<<<T, 256>>>(y);
}

// round 8
// speedup vs baseline: 1.7313x; 1.1108x over previous
#include <cuda_runtime.h>
#include <cuda_bf16.h>
#include <math.h>
#include <stdint.h>

#define HIDDEN 2048
#define INTER  768
#define NE     32
#define TOPK   8
#define MAXT   512
#define MAXP   (MAXT * TOPK)

typedef unsigned short ushort_t;

// ---- scratch (device globals) ----
__device__ float g_topw[MAXP];
__device__ int   g_topi[MAXP];
__device__ int   g_cnt[NE];
__device__ int   g_off[NE];
__device__ int   g_pt[MAXP];
__device__ int   g_t2p[MAXP];
__device__ ushort_t g_x_hi[(size_t)MAXT * HIDDEN];
__device__ ushort_t g_x_lo[(size_t)MAXT * HIDDEN];
__device__ ushort_t g_act_hi[(size_t)MAXP * INTER];
__device__ ushort_t g_act_lo[(size_t)MAXP * INTER];
__device__ float g_eout[(size_t)MAXP * HIDDEN];

// ================= helpers =================
__device__ __forceinline__ uint32_t smem_u32(const void* p) {
    uint32_t a;
    asm("{ .reg .u64 t; cvta.to.shared.u64 t, %1; cvt.u32.u64 %0, t; }" : "=r"(a) : "l"(p));
    return a;
}
__device__ __forceinline__ void cpa8z(uint32_t dst, const void* src, int zf) {
    asm volatile("cp.async.ca.shared.global [%0], [%1], 8, %2;" :: "r"(dst), "l"(src), "r"(zf));
}
#define CP_COMMIT() asm volatile("cp.async.commit_group;" ::: "memory")
#define CP_WAIT0()  asm volatile("cp.async.wait_group 0;" ::: "memory")

__device__ __forceinline__ void ldsm4(uint32_t* r, uint32_t addr) {
    asm volatile("ldmatrix.sync.aligned.m8n8.x4.shared.b16 {%0,%1,%2,%3}, [%4];"
        : "=r"(r[0]), "=r"(r[1]), "=r"(r[2]), "=r"(r[3]) : "r"(addr));
}

__device__ __forceinline__ unsigned short bfh(float v) { return __bfloat16_as_ushort(__float2bfloat16(v)); }

// cheap split: hi = truncated top-16 bits (exact residual), lo = RN-bf16 of residual
__device__ __forceinline__ void split2t(float a, float b, uint32_t& hi, uint32_t& lo) {
    uint32_t ua = __float_as_uint(a), ub = __float_as_uint(b);
    hi = __byte_perm(ua, ub, 0x7632);               // (b_hi16<<16) | a_hi16
    float ra = a - __uint_as_float(ua & 0xFFFF0000u);
    float rb = b - __uint_as_float(ub & 0xFFFF0000u);
    asm("cvt.rn.bf16x2.f32 %0, %1, %2;" : "=r"(lo) : "f"(rb), "f"(ra));
}

__device__ __forceinline__ void mma16816(float* c, const uint32_t* a, const uint32_t* b) {
    asm volatile(
        "mma.sync.aligned.m16n8k16.row.col.f32.bf16.bf16.f32 "
        "{%0,%1,%2,%3}, {%4,%5,%6,%7}, {%8,%9}, {%0,%1,%2,%3};"
        : "+f"(c[0]), "+f"(c[1]), "+f"(c[2]), "+f"(c[3])
        : "r"(a[0]), "r"(a[1]), "r"(a[2]), "r"(a[3]), "r"(b[0]), "r"(b[1]));
}

#define AS 40        // A smem row stride (ushorts); 80B rows
#define GB_ROW 1056  // e1 B row stride bytes (64n x 8B x 2c + 32 pad)
#define GB_HALF 512
#define GB_ROW2 2080 // e2 B row stride bytes (128n x 8B x 2c + 32 pad)
#define GB_HALF2 1024

// ================= small kernels =================
__global__ void prep_x_kernel(const float* __restrict__ x, int nTot) {
    int i = (blockIdx.x * 256 + threadIdx.x) * 4;
    if (i < nTot) {
        float4 v = *(const float4*)(x + i);
        uint2 H, L;
        split2t(v.x, v.y, H.x, L.x);
        split2t(v.z, v.w, H.y, L.y);
        *(uint2*)&g_x_hi[i] = H;
        *(uint2*)&g_x_lo[i] = L;
    }
}

__global__ void router_kernel(const float* __restrict__ x, const float* __restrict__ gw) {
    int t = blockIdx.x;
    __shared__ float xs[HIDDEN];
    __shared__ float logits[NE];
    int tid = threadIdx.x;
    for (int i = tid; i < HIDDEN; i += 128) xs[i] = x[(size_t)t * HIDDEN + i];
    __syncthreads();
    int warp = tid >> 5, lane = tid & 31;
    for (int e8 = 0; e8 < 8; e8++) {
        int e = warp * 8 + e8;
        const float* w = gw + (size_t)e * HIDDEN;
        float s = 0.f;
        for (int h = lane; h < HIDDEN; h += 32) s += xs[h] * w[h];
        #pragma unroll
        for (int o = 16; o; o >>= 1) s += __shfl_xor_sync(0xffffffffu, s, o);
        if (lane == 0) logits[e] = s;
    }
    __syncthreads();
    if (tid == 0) {
        float mx = -1e30f;
        for (int e = 0; e < NE; e++) mx = fmaxf(mx, logits[e]);
        float p[NE];
        for (int e = 0; e < NE; e++) p[e] = expf(logits[e] - mx);
        bool used[NE] = {};
        float wsum = 0.f; int idx[TOPK]; float wv[TOPK];
        for (int k = 0; k < TOPK; k++) {
            float best = -1.f; int bi = 0;
            for (int e = 0; e < NE; e++)
                if (!used[e] && p[e] > best) { best = p[e]; bi = e; }
            used[bi] = true; idx[k] = bi; wv[k] = best; wsum += best;
        }
        float inv = 1.f / wsum;
        for (int k = 0; k < TOPK; k++) {
            g_topi[t * TOPK + k] = idx[k];
            g_topw[t * TOPK + k] = wv[k] * inv;
        }
    }
}

__global__ void build_kernel(int T) {
    __shared__ int cnt[NE], cur[NE];
    int tid = threadIdx.x;
    int np = T * TOPK;
    if (tid < NE) cnt[tid] = 0;
    __syncthreads();
    for (int p = tid; p < np; p += blockDim.x) atomicAdd(&cnt[g_topi[p]], 1);
    __syncthreads();
    if (tid == 0) {
        int off = 0;
        for (int e = 0; e < NE; e++) {
            g_off[e] = off; g_cnt[e] = cnt[e]; cur[e] = off; off += cnt[e];
        }
    }
    __syncthreads();
    for (int p = tid; p < np; p += blockDim.x) {
        int e = g_topi[p];
        int j = atomicAdd(&cur[e], 1);
        g_pt[j] = p >> 3;
        g_t2p[p] = j;
    }
}

__global__ void combine_kernel(float* __restrict__ y) {
    int t = blockIdx.x, tid = threadIdx.x;
    __shared__ int   pj[TOPK];
    __shared__ float pw[TOPK];
    if (tid < TOPK) { pj[tid] = g_t2p[t * TOPK + tid]; pw[tid] = g_topw[t * TOPK + tid]; }
    __syncthreads();
    #pragma unroll
    for (int h = 0; h < 2; h++) {
        int c = h * 1024 + tid * 4;
        float4 acc = make_float4(0.f, 0.f, 0.f, 0.f);
        #pragma unroll
        for (int k = 0; k < TOPK; k++) {
            const float4 v = *(const float4*)(g_eout + (size_t)pj[k] * HIDDEN + c);
            float w = pw[k];
            acc.x += w * v.x; acc.y += w * v.y; acc.z += w * v.z; acc.w += w * v.w;
        }
        *(float4*)(y + (size_t)t * HIDDEN + c) = acc;
    }
}

// ================= E1 =================
// smem: toks @0 (256B) | A x2 @256 (2 x 10240) | bfG @20736 (8448) | bfU @29184 (8448)
#define E1_A    256
#define E1_BFG  20736
#define E1_BFU  29184
#define E1_SMEM 37632
#define E1_NIT  (HIDDEN / 32)

extern __shared__ __align__(16) char dsm[];

__device__ __forceinline__ void e1_prefetchA(int tid, const int* toks, uint32_t sb,
                                             int k0, int b) {
    uint32_t Abase = sb + E1_A + b * 10240;
    #pragma unroll
    for (int q = 0; q < 2; q++) {
        int lin = q * 256 + tid;
        int m = lin >> 3, c = lin & 7;
        int t = toks[m];
        int zf = (t >= 0) ? 8 : 0;
        size_t so = (size_t)(t >= 0 ? t : 0) * HIDDEN + k0 + c * 4;
        uint32_t d = Abase + m * 80 + c * 8;
        cpa8z(d, g_x_hi + so, zf);
        cpa8z(d + 5120, g_x_lo + so, zf);
    }
    CP_COMMIT();
}

__global__ __launch_bounds__(256, 2)
void e1_kernel(const float* __restrict__ gate_proj,
               const float* __restrict__ up_proj) {
    int e = blockIdx.x;
    int n = g_cnt[e];
    int mbase = blockIdx.y * 64;
    if (mbase >= n) return;
    int off = g_off[e];
    int nbase = blockIdx.z * 64;

    uint32_t sb = smem_u32(dsm);
    int tid = threadIdx.x, wid = tid >> 5, lane = tid & 31;
    int* toks = (int*)dsm;
    if (tid < 64) { int m = mbase + tid; toks[tid] = (m < n) ? g_pt[off + m] : -1; }
    __syncthreads();

    const float* gp  = gate_proj + (size_t)e * HIDDEN * INTER + nbase;
    const float* up_ = up_proj   + (size_t)e * HIDDEN * INTER + nbase;

    int wm = wid >> 2, wn = wid & 3;
    int g = lane >> 2, tg = lane & 3;
    int lq = lane >> 3, lr = lane & 7;
    int lmoff = ((lq & 1) * 8 + lr) * (AS * 2) + (lq >> 1) * 16;

    int nn = tid & 63, kg = tid >> 6;

    float accg[2][2][4] = {};
    float accu[2][2][4] = {};
    float gv[4][2], uv[4][2];

    // weight LDG (one iter ahead, into regs)
    auto ldw = [&](int k0) {
        #pragma unroll
        for (int kpi = 0; kpi < 4; kpi++) {
            int k = (kpi * 4 + kg) * 2;
            const float* pg = gp + (size_t)(k0 + k) * INTER + nn;
            const float* pu = up_ + (size_t)(k0 + k) * INTER + nn;
            gv[kpi][0] = pg[0]; gv[kpi][1] = pg[INTER];
            uv[kpi][0] = pu[0]; uv[kpi][1] = pu[INTER];
        }
    };

    ldw(0);
    e1_prefetchA(tid, toks, sb, 0, 0);

    for (int it = 0; it < E1_NIT; it++) {
        int b = it & 1;
        CP_WAIT0();
        __syncthreads();
        if (it + 1 < E1_NIT)
            e1_prefetchA(tid, toks, sb, (it + 1) * 32, b ^ 1);

        // ---- convert regs -> bf smem ([r][c][n]{hi,lo}) ----
        #pragma unroll
        for (int kpi = 0; kpi < 4; kpi++) {
            int kp = kpi * 4 + kg;
            int r = (kp & 3) | ((kp >> 3) << 2);
            int c = (kp >> 2) & 1;
            uint32_t hi, lo;
            split2t(gv[kpi][0], gv[kpi][1], hi, lo);
            *(uint2*)(dsm + E1_BFG + r * GB_ROW + c * GB_HALF + nn * 8) = make_uint2(hi, lo);
            split2t(uv[kpi][0], uv[kpi][1], hi, lo);
            *(uint2*)(dsm + E1_BFU + r * GB_ROW + c * GB_HALF + nn * 8) = make_uint2(hi, lo);
        }
        if (it + 1 < E1_NIT) ldw((it + 1) * 32);
        __syncthreads();

        uint32_t Ah_base = sb + E1_A + b * 10240 + (wm * 32) * 80 + lmoff;
        #pragma unroll
        for (int kk = 0; kk < 32; kk += 16) {
            uint32_t ah[2][4], al[2][4];
            #pragma unroll
            for (int mf = 0; mf < 2; mf++) {
                uint32_t aaddr = Ah_base + mf * (16 * 80) + kk * 2;
                ldsm4(ah[mf], aaddr);
                ldsm4(al[mf], aaddr + 5120);
            }
            const char* Grow = dsm + E1_BFG + (tg + (kk >> 2)) * GB_ROW;
            const char* Urow = dsm + E1_BFU + (tg + (kk >> 2)) * GB_ROW;
            {
                uint32_t bh[2][2], bl[2][2];
                #pragma unroll
                for (int nf = 0; nf < 2; nf++) {
                    int nb = (wn * 16 + nf * 8 + g) * 8;
                    uint2 v0 = *(const uint2*)(Grow + nb);
                    uint2 v1 = *(const uint2*)(Grow + GB_HALF + nb);
                    bh[nf][0] = v0.x; bl[nf][0] = v0.y;
                    bh[nf][1] = v1.x; bl[nf][1] = v1.y;
                }
                #pragma unroll
                for (int mf = 0; mf < 2; mf++)
                #pragma unroll
                for (int nf = 0; nf < 2; nf++) {
                    mma16816(accg[mf][nf], ah[mf], bh[nf]);
                    mma16816(accg[mf][nf], ah[mf], bl[nf]);
                    mma16816(accg[mf][nf], al[mf], bh[nf]);
                }
            }
            {
                uint32_t bh[2][2], bl[2][2];
                #pragma unroll
                for (int nf = 0; nf < 2; nf++) {
                    int nb = (wn * 16 + nf * 8 + g) * 8;
                    uint2 v0 = *(const uint2*)(Urow + nb);
                    uint2 v1 = *(const uint2*)(Urow + GB_HALF + nb);
                    bh[nf][0] = v0.x; bl[nf][0] = v0.y;
                    bh[nf][1] = v1.x; bl[nf][1] = v1.y;
                }
                #pragma unroll
                for (int mf = 0; mf < 2; mf++)
                #pragma unroll
                for (int nf = 0; nf < 2; nf++) {
                    mma16816(accu[mf][nf], ah[mf], bh[nf]);
                    mma16816(accu[mf][nf], ah[mf], bl[nf]);
                    mma16816(accu[mf][nf], al[mf], bh[nf]);
                }
            }
        }
        __syncthreads();
    }

    // ---- epilogue: silu(g)*u -> split bf16 -> g_act ----
    #pragma unroll
    for (int mf = 0; mf < 2; mf++)
    #pragma unroll
    for (int nf = 0; nf < 2; nf++)
    #pragma unroll
    for (int i = 0; i < 4; i++) {
        int m = mbase + wm * 32 + mf * 16 + g + (i >> 1) * 8;
        if (m >= n) continue;
        int col = nbase + wn * 16 + nf * 8 + 2 * tg + (i & 1);
        float gvv = accg[mf][nf][i], uvv = accu[mf][nf][i];
        float a = (gvv / (1.f + __expf(-gvv))) * uvv;
        uint32_t ua = __float_as_uint(a);
        float r = a - __uint_as_float(ua & 0xFFFF0000u);
        size_t ai = (size_t)(off + m) * INTER + col;
        g_act_hi[ai] = (ushort_t)(ua >> 16);
        g_act_lo[ai] = bfh(r);
    }
}

// ================= E2 (M64 x N128) =================
// smem: A x2 @0 (2 x 10240) | bfB @20480 (16640)
#define E2_A    0
#define E2_BF   20480
#define E2_SMEM 37120
#define E2_NIT  (INTER / 32)

__device__ __forceinline__ void e2_prefetchA(int tid, int off, int mbase, int n, uint32_t sb,
                                             int k0, int b) {
    uint32_t Abase = sb + E2_A + b * 10240;
    #pragma unroll
    for (int q = 0; q < 2; q++) {
        int lin = q * 256 + tid;
        int m = lin >> 3, c = lin & 7;
        bool valid = (mbase + m) < n;
        int zf = valid ? 8 : 0;
        size_t so = valid ? ((size_t)(off + mbase + m) * INTER + k0 + c * 4) : 0;
        uint32_t d = Abase + m * 80 + c * 8;
        cpa8z(d, g_act_hi + so, zf);
        cpa8z(d + 5120, g_act_lo + so, zf);
    }
    CP_COMMIT();
}

__global__ __launch_bounds__(256, 2)
void e2_kernel(const float* __restrict__ down_proj) {
    int e = blockIdx.x;
    int n = g_cnt[e];
    int mbase = blockIdx.y * 64;
    if (mbase >= n) return;
    int off = g_off[e];
    int nbase = blockIdx.z * 128;

    uint32_t sb = smem_u32(dsm);
    int tid = threadIdx.x, wid = tid >> 5, lane = tid & 31;
    int wm = wid >> 2, wn = wid & 3;
    int g = lane >> 2, tg = lane & 3;
    int lq = lane >> 3, lr = lane & 7;
    int lmoff = ((lq & 1) * 8 + lr) * (AS * 2) + (lq >> 1) * 16;

    int nn = tid & 127, kg = tid >> 7;

    const float* dp = down_proj + (size_t)e * INTER * HIDDEN + nbase;

    float acc[2][4][4] = {};
    float bv[8][2];

    auto ldw = [&](int k0) {
        #pragma unroll
        for (int kpi = 0; kpi < 8; kpi++) {
            int k = (kpi * 2 + kg) * 2;
            const float* pb = dp + (size_t)(k0 + k) * HIDDEN + nn;
            bv[kpi][0] = pb[0]; bv[kpi][1] = pb[HIDDEN];
        }
    };

    ldw(0);
    e2_prefetchA(tid, off, mbase, n, sb, 0, 0);

    for (int it = 0; it < E2_NIT; it++) {
        int b = it & 1;
        CP_WAIT0();
        __syncthreads();
        if (it + 1 < E2_NIT)
            e2_prefetchA(tid, off, mbase, n, sb, (it + 1) * 32, b ^ 1);

        #pragma unroll
        for (int kpi = 0; kpi < 8; kpi++) {
            int kp = kpi * 2 + kg;
            int r = (kp & 3) | ((kp >> 3) << 2);
            int c = (kp >> 2) & 1;
            uint32_t hi, lo;
            split2t(bv[kpi][0], bv[kpi][1], hi, lo);
            *(uint2*)(dsm + E2_BF + r * GB_ROW2 + c * GB_HALF2 + nn * 8) = make_uint2(hi, lo);
        }
        if (it + 1 < E2_NIT) ldw((it + 1) * 32);
        __syncthreads();

        uint32_t Ah_base = sb + E2_A + b * 10240 + (wm * 32) * 80 + lmoff;
        #pragma unroll
        for (int kk = 0; kk < 32; kk += 16) {
            uint32_t ah[2][4], al[2][4];
            #pragma unroll
            for (int mf = 0; mf < 2; mf++) {
                uint32_t aaddr = Ah_base + mf * (16 * 80) + kk * 2;
                ldsm4(ah[mf], aaddr);
                ldsm4(al[mf], aaddr + 5120);
            }
            const char* Brow = dsm + E2_BF + (tg + (kk >> 2)) * GB_ROW2;
            uint32_t bh[4][2], bl[4][2];
            #pragma unroll
            for (int nf = 0; nf < 4; nf++) {
                int nb = (wn * 32 + nf * 8 + g) * 8;
                uint2 v0 = *(const uint2*)(Brow + nb);
                uint2 v1 = *(const uint2*)(Brow + GB_HALF2 + nb);
                bh[nf][0] = v0.x; bl[nf][0] = v0.y;
                bh[nf][1] = v1.x; bl[nf][1] = v1.y;
            }
            #pragma unroll
            for (int mf = 0; mf < 2; mf++)
            #pragma unroll
            for (int nf = 0; nf < 4; nf++) {
                mma16816(acc[mf][nf], ah[mf], bh[nf]);
                mma16816(acc[mf][nf], ah[mf], bl[nf]);
                mma16816(acc[mf][nf], al[mf], bh[nf]);
            }
        }
        __syncthreads();
    }

    // ---- epilogue: raw per-pair output rows ----
    #pragma unroll
    for (int mf = 0; mf < 2; mf++) {
        #pragma unroll
        for (int half = 0; half < 2; half++) {
            int m = mbase + wm * 32 + mf * 16 + g + half * 8;
            if (m >= n) continue;
            float* orow = g_eout + (size_t)(off + m) * HIDDEN + nbase;
            #pragma unroll
            for (int nf = 0; nf < 4; nf++) {
                int col = wn * 32 + nf * 8 + 2 * tg;
                float2 v = make_float2(acc[mf][nf][half * 2], acc[mf][nf][half * 2 + 1]);
                *(float2*)&orow[col] = v;
            }
        }
    }
}

// ================= launch =================
extern "C" void kernel_launch(void* const* d_in, const int* in_sizes, int n_in,
                              void* d_out, int out_size) {
    const float* x  = (const float*)d_in[0];
    const float* gw = (const float*)d_in[1];
    const float* gp = (const float*)d_in[2];
    const float* up = (const float*)d_in[3];
    const float* dp = (const float*)d_in[4];
    float* y = (float*)d_out;

    int T = in_sizes[0] / HIDDEN;
    int nTot = T * HIDDEN;

    prep_x_kernel<<<(nTot / 4 + 255) / 256, 256>>>(x, nTot);
    router_kernel<<<T, 128>>>(x, gw);
    build_kernel<<<1, 512>>>(T);

    dim3 g1(NE, (T + 63) / 64, INTER / 64);    // (32, 8, 12)
    e1_kernel<<<g1, 256, E1_SMEM>>>(gp, up);

    dim3 g2(NE, (T + 63) / 64, HIDDEN / 128);  // (32, 8, 16)
    e2_kernel<<<g2, 256, E2_SMEM>>>(dp);

    combine_kernel<<<T, 256>>>(y);
}

// round 9
// speedup vs baseline: 1.8750x; 1.0830x over previous
#include <cuda_runtime.h>
#include <cuda_bf16.h>
#include <math.h>
#include <stdint.h>

#define HIDDEN 2048
#define INTER  768
#define NE     32
#define TOPK   8
#define MAXT   512
#define MAXP   (MAXT * TOPK)

typedef unsigned short ushort_t;

// ---- scratch (device globals) ----
__device__ float g_topw[MAXP];
__device__ int   g_topi[MAXP];
__device__ int   g_cnt[NE];
__device__ int   g_off[NE];
__device__ int   g_pt[MAXP];
__device__ int   g_t2p[MAXP];
__device__ ushort_t g_x_hi[(size_t)MAXT * HIDDEN];
__device__ ushort_t g_x_lo[(size_t)MAXT * HIDDEN];
__device__ ushort_t g_act_hi[(size_t)MAXP * INTER];
__device__ ushort_t g_act_lo[(size_t)MAXP * INTER];
__device__ float g_eout[(size_t)MAXP * HIDDEN];

// ================= helpers =================
__device__ __forceinline__ uint32_t smem_u32(const void* p) {
    uint32_t a;
    asm("{ .reg .u64 t; cvta.to.shared.u64 t, %1; cvt.u32.u64 %0, t; }" : "=r"(a) : "l"(p));
    return a;
}
__device__ __forceinline__ void cpa16z(uint32_t dst, const void* src, int zf) {
    asm volatile("cp.async.ca.shared.global [%0], [%1], 16, %2;" :: "r"(dst), "l"(src), "r"(zf));
}
#define CP_COMMIT() asm volatile("cp.async.commit_group;" ::: "memory")
#define CP_WAIT0()  asm volatile("cp.async.wait_group 0;" ::: "memory")
#define CP_WAIT1()  asm volatile("cp.async.wait_group 1;" ::: "memory")

__device__ __forceinline__ void ldsm4(uint32_t* r, uint32_t addr) {
    asm volatile("ldmatrix.sync.aligned.m8n8.x4.shared.b16 {%0,%1,%2,%3}, [%4];"
        : "=r"(r[0]), "=r"(r[1]), "=r"(r[2]), "=r"(r[3]) : "r"(addr));
}

__device__ __forceinline__ unsigned short bfh(float v) { return __bfloat16_as_ushort(__float2bfloat16(v)); }

// cheap split: hi = truncated top-16 bits (exact residual), lo = RN-bf16 of residual
__device__ __forceinline__ void split2t(float a, float b, uint32_t& hi, uint32_t& lo) {
    uint32_t ua = __float_as_uint(a), ub = __float_as_uint(b);
    hi = __byte_perm(ua, ub, 0x7632);
    float ra = a - __uint_as_float(ua & 0xFFFF0000u);
    float rb = b - __uint_as_float(ub & 0xFFFF0000u);
    asm("cvt.rn.bf16x2.f32 %0, %1, %2;" : "=r"(lo) : "f"(rb), "f"(ra));
}

__device__ __forceinline__ void mma16816(float* c, const uint32_t* a, const uint32_t* b) {
    asm volatile(
        "mma.sync.aligned.m16n8k16.row.col.f32.bf16.bf16.f32 "
        "{%0,%1,%2,%3}, {%4,%5,%6,%7}, {%8,%9}, {%0,%1,%2,%3};"
        : "+f"(c[0]), "+f"(c[1]), "+f"(c[2]), "+f"(c[3])
        : "r"(a[0]), "r"(a[1]), "r"(a[2]), "r"(a[3]), "r"(b[0]), "r"(b[1]));
}

#define AS 40        // A smem row stride (ushorts); 80B rows
#define GB_ROW 1056  // e1 B row stride bytes
#define GB_HALF 512
#define GB_ROW2 2080 // e2 B row stride bytes
#define GB_HALF2 1024

// ================= small kernels =================
__global__ void prep_x_kernel(const float* __restrict__ x, int nTot) {
    int i = (blockIdx.x * 256 + threadIdx.x) * 4;
    if (i < nTot) {
        float4 v = *(const float4*)(x + i);
        uint2 H, L;
        split2t(v.x, v.y, H.x, L.x);
        split2t(v.z, v.w, H.y, L.y);
        *(uint2*)&g_x_hi[i] = H;
        *(uint2*)&g_x_lo[i] = L;
    }
}

__global__ void router_kernel(const float* __restrict__ x, const float* __restrict__ gw) {
    int t = blockIdx.x;
    __shared__ float xs[HIDDEN];
    __shared__ float logits[NE];
    int tid = threadIdx.x;
    for (int i = tid; i < HIDDEN; i += 128) xs[i] = x[(size_t)t * HIDDEN + i];
    __syncthreads();
    int warp = tid >> 5, lane = tid & 31;
    for (int e8 = 0; e8 < 8; e8++) {
        int e = warp * 8 + e8;
        const float* w = gw + (size_t)e * HIDDEN;
        float s = 0.f;
        for (int h = lane; h < HIDDEN; h += 32) s += xs[h] * w[h];
        #pragma unroll
        for (int o = 16; o; o >>= 1) s += __shfl_xor_sync(0xffffffffu, s, o);
        if (lane == 0) logits[e] = s;
    }
    __syncthreads();
    if (tid == 0) {
        float mx = -1e30f;
        for (int e = 0; e < NE; e++) mx = fmaxf(mx, logits[e]);
        float p[NE];
        for (int e = 0; e < NE; e++) p[e] = expf(logits[e] - mx);
        bool used[NE] = {};
        float wsum = 0.f; int idx[TOPK]; float wv[TOPK];
        for (int k = 0; k < TOPK; k++) {
            float best = -1.f; int bi = 0;
            for (int e = 0; e < NE; e++)
                if (!used[e] && p[e] > best) { best = p[e]; bi = e; }
            used[bi] = true; idx[k] = bi; wv[k] = best; wsum += best;
        }
        float inv = 1.f / wsum;
        for (int k = 0; k < TOPK; k++) {
            g_topi[t * TOPK + k] = idx[k];
            g_topw[t * TOPK + k] = wv[k] * inv;
        }
    }
}

__global__ void build_kernel(int T) {
    __shared__ int cnt[NE], cur[NE];
    int tid = threadIdx.x;
    int np = T * TOPK;
    if (tid < NE) cnt[tid] = 0;
    __syncthreads();
    for (int p = tid; p < np; p += blockDim.x) atomicAdd(&cnt[g_topi[p]], 1);
    __syncthreads();
    if (tid == 0) {
        int off = 0;
        for (int e = 0; e < NE; e++) {
            g_off[e] = off; g_cnt[e] = cnt[e]; cur[e] = off; off += cnt[e];
        }
    }
    __syncthreads();
    for (int p = tid; p < np; p += blockDim.x) {
        int e = g_topi[p];
        int j = atomicAdd(&cur[e], 1);
        g_pt[j] = p >> 3;
        g_t2p[p] = j;
    }
}

__global__ void combine_kernel(float* __restrict__ y) {
    int t = blockIdx.x, tid = threadIdx.x;
    __shared__ int   pj[TOPK];
    __shared__ float pw[TOPK];
    if (tid < TOPK) { pj[tid] = g_t2p[t * TOPK + tid]; pw[tid] = g_topw[t * TOPK + tid]; }
    __syncthreads();
    #pragma unroll
    for (int h = 0; h < 2; h++) {
        int c = h * 1024 + tid * 4;
        float4 acc = make_float4(0.f, 0.f, 0.f, 0.f);
        #pragma unroll
        for (int k = 0; k < TOPK; k++) {
            const float4 v = *(const float4*)(g_eout + (size_t)pj[k] * HIDDEN + c);
            float w = pw[k];
            acc.x += w * v.x; acc.y += w * v.y; acc.z += w * v.z; acc.w += w * v.w;
        }
        *(float4*)(y + (size_t)t * HIDDEN + c) = acc;
    }
}

// ================= E1 =================
// smem: toks @0 (256B) | A x3 @256 (3 x 10240) | B x2 @30976 (2 x (G8448+U8448))
#define E1_A    256
#define E1_B    30976
#define E1_BSZ  16896
#define E1_SMEM 64768
#define E1_NIT  (HIDDEN / 32)

extern __shared__ __align__(16) char dsm[];

__device__ __forceinline__ void e1_prefA(int tid, const int* toks, uint32_t sb,
                                         int k0, uint32_t abuf) {
    int m = tid >> 2, c4 = tid & 3;
    int t = toks[m];
    int zf = (t >= 0) ? 16 : 0;
    size_t so = (size_t)(t >= 0 ? t : 0) * HIDDEN + k0 + c4 * 8;
    uint32_t d = sb + E1_A + abuf + m * 80 + c4 * 16;
    cpa16z(d, g_x_hi + so, zf);
    cpa16z(d + 5120, g_x_lo + so, zf);
    CP_COMMIT();
}

__global__ __launch_bounds__(256, 2)
void e1_kernel(const float* __restrict__ gate_proj,
               const float* __restrict__ up_proj) {
    int e = blockIdx.x;
    int n = g_cnt[e];
    int mbase = blockIdx.y * 64;
    if (mbase >= n) return;
    int off = g_off[e];
    int nbase = blockIdx.z * 64;

    uint32_t sb = smem_u32(dsm);
    int tid = threadIdx.x, wid = tid >> 5, lane = tid & 31;
    int* toks = (int*)dsm;
    if (tid < 64) { int m = mbase + tid; toks[tid] = (m < n) ? g_pt[off + m] : -1; }
    __syncthreads();

    const float* gp  = gate_proj + (size_t)e * HIDDEN * INTER + nbase;
    const float* up_ = up_proj   + (size_t)e * HIDDEN * INTER + nbase;

    int wm = wid >> 2, wn = wid & 3;
    int g = lane >> 2, tg = lane & 3;
    int lq = lane >> 3, lr = lane & 7;
    int lmoff = ((lq & 1) * 8 + lr) * (AS * 2) + (lq >> 1) * 16;

    int nn2 = tid & 31, kg = tid >> 5;     // n-pair id, k-group

    float accg[2][2][4] = {};
    float accu[2][2][4] = {};
    float2 gv2[2][2], uv2[2][2];

    // weight LDG (consumed one iter later by convert)
    auto ldw = [&](int k0) {
        #pragma unroll
        for (int kpi = 0; kpi < 2; kpi++) {
            int k = (kpi * 8 + kg) * 2;
            const float* pg = gp + (size_t)(k0 + k) * INTER + nn2 * 2;
            const float* pu = up_ + (size_t)(k0 + k) * INTER + nn2 * 2;
            gv2[kpi][0] = *(const float2*)pg;
            gv2[kpi][1] = *(const float2*)(pg + INTER);
            uv2[kpi][0] = *(const float2*)pu;
            uv2[kpi][1] = *(const float2*)(pu + INTER);
        }
    };
    // convert regs -> B buffer (layout [r][c][n]{hi,lo}, 16B per n-pair)
    auto conv = [&](uint32_t bp_dst) {
        #pragma unroll
        for (int kpi = 0; kpi < 2; kpi++) {
            int kp = kpi * 8 + kg;
            int r = (kp & 3) | ((kp >> 3) << 2);
            int c = (kp >> 2) & 1;
            char* base = dsm + E1_B + bp_dst + r * GB_ROW + c * GB_HALF + nn2 * 16;
            uint4 o;
            split2t(gv2[kpi][0].x, gv2[kpi][1].x, o.x, o.y);
            split2t(gv2[kpi][0].y, gv2[kpi][1].y, o.z, o.w);
            *(uint4*)base = o;
            split2t(uv2[kpi][0].x, uv2[kpi][1].x, o.x, o.y);
            split2t(uv2[kpi][0].y, uv2[kpi][1].y, o.z, o.w);
            *(uint4*)(base + 8448) = o;
        }
    };

    // prologue
    ldw(0);
    e1_prefA(tid, toks, sb, 0, 0);
    conv(0);
    ldw(32);
    e1_prefA(tid, toks, sb, 32, 10240);
    CP_WAIT1();
    __syncthreads();

    uint32_t ap_r = 0, ap_w = 20480, bp = 0;
    for (int it = 0; it < E1_NIT; it++) {
        // ---- MMA(it): A[ap_r], B[bp] ----
        uint32_t Ah_base = sb + E1_A + ap_r + (wm * 32) * 80 + lmoff;
        #pragma unroll
        for (int kk = 0; kk < 32; kk += 16) {
            uint32_t ah[2][4], al[2][4];
            #pragma unroll
            for (int mf = 0; mf < 2; mf++) {
                uint32_t aaddr = Ah_base + mf * (16 * 80) + kk * 2;
                ldsm4(ah[mf], aaddr);
                ldsm4(al[mf], aaddr + 5120);
            }
            const char* Grow = dsm + E1_B + bp + (tg + (kk >> 2)) * GB_ROW;
            {
                uint32_t bh[2][2], bl[2][2];
                #pragma unroll
                for (int nf = 0; nf < 2; nf++) {
                    int nb = (wn * 16 + nf * 8 + g) * 8;
                    uint2 v0 = *(const uint2*)(Grow + nb);
                    uint2 v1 = *(const uint2*)(Grow + GB_HALF + nb);
                    bh[nf][0] = v0.x; bl[nf][0] = v0.y;
                    bh[nf][1] = v1.x; bl[nf][1] = v1.y;
                }
                #pragma unroll
                for (int mf = 0; mf < 2; mf++)
                #pragma unroll
                for (int nf = 0; nf < 2; nf++) {
                    mma16816(accg[mf][nf], ah[mf], bh[nf]);
                    mma16816(accg[mf][nf], ah[mf], bl[nf]);
                    mma16816(accg[mf][nf], al[mf], bh[nf]);
                }
            }
            {
                const char* Urow = Grow + 8448;
                uint32_t bh[2][2], bl[2][2];
                #pragma unroll
                for (int nf = 0; nf < 2; nf++) {
                    int nb = (wn * 16 + nf * 8 + g) * 8;
                    uint2 v0 = *(const uint2*)(Urow + nb);
                    uint2 v1 = *(const uint2*)(Urow + GB_HALF + nb);
                    bh[nf][0] = v0.x; bl[nf][0] = v0.y;
                    bh[nf][1] = v1.x; bl[nf][1] = v1.y;
                }
                #pragma unroll
                for (int mf = 0; mf < 2; mf++)
                #pragma unroll
                for (int nf = 0; nf < 2; nf++) {
                    mma16816(accu[mf][nf], ah[mf], bh[nf]);
                    mma16816(accu[mf][nf], ah[mf], bl[nf]);
                    mma16816(accu[mf][nf], al[mf], bh[nf]);
                }
            }
        }

        // ---- convert(it+1) into other B buffer (overlaps tensor drain) ----
        if (it + 1 < E1_NIT) conv(bp ^ E1_BSZ);
        // ---- prefetch it+2 ----
        if (it + 2 < E1_NIT) {
            ldw((it + 2) * 32);
            e1_prefA(tid, toks, sb, (it + 2) * 32, ap_w);
            CP_WAIT1();
        } else if (it + 1 < E1_NIT) {
            CP_WAIT0();
        }
        __syncthreads();
        bp ^= E1_BSZ;
        ap_r = (ap_r == 20480) ? 0 : ap_r + 10240;
        ap_w = (ap_w == 20480) ? 0 : ap_w + 10240;
    }

    // ---- epilogue: silu(g)*u -> split bf16 -> g_act ----
    #pragma unroll
    for (int mf = 0; mf < 2; mf++)
    #pragma unroll
    for (int nf = 0; nf < 2; nf++)
    #pragma unroll
    for (int i = 0; i < 4; i++) {
        int m = mbase + wm * 32 + mf * 16 + g + (i >> 1) * 8;
        if (m >= n) continue;
        int col = nbase + wn * 16 + nf * 8 + 2 * tg + (i & 1);
        float gvv = accg[mf][nf][i], uvv = accu[mf][nf][i];
        float a = (gvv / (1.f + __expf(-gvv))) * uvv;
        uint32_t ua = __float_as_uint(a);
        float r = a - __uint_as_float(ua & 0xFFFF0000u);
        size_t ai = (size_t)(off + m) * INTER + col;
        g_act_hi[ai] = (ushort_t)(ua >> 16);
        g_act_lo[ai] = bfh(r);
    }
}

// ================= E2 (M64 x N128) =================
// smem: A x3 @0 (3 x 10240) | B x2 @30720 (2 x 16640)
#define E2_A    0
#define E2_B    30720
#define E2_BSZ  16640
#define E2_SMEM 64000
#define E2_NIT  (INTER / 32)

__device__ __forceinline__ void e2_prefA(int tid, int off, int mbase, int n, uint32_t sb,
                                         int k0, uint32_t abuf) {
    int m = tid >> 2, c4 = tid & 3;
    bool valid = (mbase + m) < n;
    int zf = valid ? 16 : 0;
    size_t so = valid ? ((size_t)(off + mbase + m) * INTER + k0 + c4 * 8) : 0;
    uint32_t d = sb + E2_A + abuf + m * 80 + c4 * 16;
    cpa16z(d, g_act_hi + so, zf);
    cpa16z(d + 5120, g_act_lo + so, zf);
    CP_COMMIT();
}

__global__ __launch_bounds__(256, 2)
void e2_kernel(const float* __restrict__ down_proj) {
    int e = blockIdx.x;
    int n = g_cnt[e];
    int mbase = blockIdx.y * 64;
    if (mbase >= n) return;
    int off = g_off[e];
    int nbase = blockIdx.z * 128;

    uint32_t sb = smem_u32(dsm);
    int tid = threadIdx.x, wid = tid >> 5, lane = tid & 31;
    int wm = wid >> 2, wn = wid & 3;
    int g = lane >> 2, tg = lane & 3;
    int lq = lane >> 3, lr = lane & 7;
    int lmoff = ((lq & 1) * 8 + lr) * (AS * 2) + (lq >> 1) * 16;

    int nn2 = tid & 63, kg = tid >> 6;

    const float* dp = down_proj + (size_t)e * INTER * HIDDEN + nbase;

    float acc[2][4][4] = {};
    float2 bv2[4][2];

    auto ldw = [&](int k0) {
        #pragma unroll
        for (int kpi = 0; kpi < 4; kpi++) {
            int k = (kpi * 4 + kg) * 2;
            const float* pb = dp + (size_t)(k0 + k) * HIDDEN + nn2 * 2;
            bv2[kpi][0] = *(const float2*)pb;
            bv2[kpi][1] = *(const float2*)(pb + HIDDEN);
        }
    };
    auto conv = [&](uint32_t bp_dst) {
        #pragma unroll
        for (int kpi = 0; kpi < 4; kpi++) {
            int kp = kpi * 4 + kg;
            int r = (kp & 3) | ((kp >> 3) << 2);
            int c = (kp >> 2) & 1;
            char* base = dsm + E2_B + bp_dst + r * GB_ROW2 + c * GB_HALF2 + nn2 * 16;
            uint4 o;
            split2t(bv2[kpi][0].x, bv2[kpi][1].x, o.x, o.y);
            split2t(bv2[kpi][0].y, bv2[kpi][1].y, o.z, o.w);
            *(uint4*)base = o;
        }
    };

    ldw(0);
    e2_prefA(tid, off, mbase, n, sb, 0, 0);
    conv(0);
    ldw(32);
    e2_prefA(tid, off, mbase, n, sb, 32, 10240);
    CP_WAIT1();
    __syncthreads();

    uint32_t ap_r = 0, ap_w = 20480, bp = 0;
    for (int it = 0; it < E2_NIT; it++) {
        uint32_t Ah_base = sb + E2_A + ap_r + (wm * 32) * 80 + lmoff;
        #pragma unroll
        for (int kk = 0; kk < 32; kk += 16) {
            uint32_t ah[2][4], al[2][4];
            #pragma unroll
            for (int mf = 0; mf < 2; mf++) {
                uint32_t aaddr = Ah_base + mf * (16 * 80) + kk * 2;
                ldsm4(ah[mf], aaddr);
                ldsm4(al[mf], aaddr + 5120);
            }
            const char* Brow = dsm + E2_B + bp + (tg + (kk >> 2)) * GB_ROW2;
            uint32_t bh[4][2], bl[4][2];
            #pragma unroll
            for (int nf = 0; nf < 4; nf++) {
                int nb = (wn * 32 + nf * 8 + g) * 8;
                uint2 v0 = *(const uint2*)(Brow + nb);
                uint2 v1 = *(const uint2*)(Brow + GB_HALF2 + nb);
                bh[nf][0] = v0.x; bl[nf][0] = v0.y;
                bh[nf][1] = v1.x; bl[nf][1] = v1.y;
            }
            #pragma unroll
            for (int mf = 0; mf < 2; mf++)
            #pragma unroll
            for (int nf = 0; nf < 4; nf++) {
                mma16816(acc[mf][nf], ah[mf], bh[nf]);
                mma16816(acc[mf][nf], ah[mf], bl[nf]);
                mma16816(acc[mf][nf], al[mf], bh[nf]);
            }
        }

        if (it + 1 < E2_NIT) conv(bp ^ E2_BSZ);
        if (it + 2 < E2_NIT) {
            ldw((it + 2) * 32);
            e2_prefA(tid, off, mbase, n, sb, (it + 2) * 32, ap_w);
            CP_WAIT1();
        } else if (it + 1 < E2_NIT) {
            CP_WAIT0();
        }
        __syncthreads();
        bp ^= E2_BSZ;
        ap_r = (ap_r == 20480) ? 0 : ap_r + 10240;
        ap_w = (ap_w == 20480) ? 0 : ap_w + 10240;
    }

    // ---- epilogue: raw per-pair output rows ----
    #pragma unroll
    for (int mf = 0; mf < 2; mf++) {
        #pragma unroll
        for (int half = 0; half < 2; half++) {
            int m = mbase + wm * 32 + mf * 16 + g + half * 8;
            if (m >= n) continue;
            float* orow = g_eout + (size_t)(off + m) * HIDDEN + nbase;
            #pragma unroll
            for (int nf = 0; nf < 4; nf++) {
                int col = wn * 32 + nf * 8 + 2 * tg;
                float2 v = make_float2(acc[mf][nf][half * 2], acc[mf][nf][half * 2 + 1]);
                *(float2*)&orow[col] = v;
            }
        }
    }
}

// ================= launch =================
extern "C" void kernel_launch(void* const* d_in, const int* in_sizes, int n_in,
                              void* d_out, int out_size) {
    const float* x  = (const float*)d_in[0];
    const float* gw = (const float*)d_in[1];
    const float* gp = (const float*)d_in[2];
    const float* up = (const float*)d_in[3];
    const float* dp = (const float*)d_in[4];
    float* y = (float*)d_out;

    int T = in_sizes[0] / HIDDEN;
    int nTot = T * HIDDEN;

    cudaFuncSetAttribute(e1_kernel, cudaFuncAttributeMaxDynamicSharedMemorySize, E1_SMEM);
    cudaFuncSetAttribute(e2_kernel, cudaFuncAttributeMaxDynamicSharedMemorySize, E2_SMEM);

    prep_x_kernel<<<(nTot / 4 + 255) / 256, 256>>>(x, nTot);
    router_kernel<<<T, 128>>>(x, gw);
    build_kernel<<<1, 512>>>(T);

    dim3 g1(NE, (T + 63) / 64, INTER / 64);    // (32, 8, 12)
    e1_kernel<<<g1, 256, E1_SMEM>>>(gp, up);

    dim3 g2(NE, (T + 63) / 64, HIDDEN / 128);  // (32, 8, 16)
    e2_kernel<<<g2, 256, E2_SMEM>>>(dp);

    combine_kernel<<<T, 256>>>(y);
}